// round 9
// baseline (speedup 1.0000x reference)
#include <cuda_runtime.h>
#include <cuda_bf16.h>
#include <math.h>
#include <stdint.h>

#define D_MODEL 1024
#define HDIM    512
#define SLOTS   4096
#define LEVELS  3
#define NTOK    16384
#define TOPK    8
#define CAND    16

typedef unsigned long long ull;
typedef unsigned int u32;

// ---------------- scratch (static __device__, no allocations) ----------------
__device__ int8_t g_qi8[(size_t)NTOK * D_MODEL];                  // 16 MB int8 q
__device__ int8_t g_ki8[(size_t)LEVELS * SLOTS * D_MODEL];        // 12 MB int8 K
__device__ float  g_sq[NTOK];                                     // per-token scale
__device__ float  g_sk[LEVELS * SLOTS];                           // per-slot scale
__device__ float  g_h[(size_t)NTOK * HDIM];                       // router hidden
__device__ float  g_route[NTOK * LEVELS];                         // route weights
__device__ int    g_ci[(size_t)LEVELS * NTOK * CAND];             // top-16 candidates

// ---------------- PTX helpers (baseline-ISA only) ----------------
__device__ __forceinline__ void cp16(u32 dst, const void* src) {
    asm volatile("cp.async.cg.shared.global [%0], [%1], 16;" :: "r"(dst), "l"(src) : "memory");
}
#define CP_COMMIT() asm volatile("cp.async.commit_group;" ::: "memory")
#define CP_WAIT2()  asm volatile("cp.async.wait_group 2;" ::: "memory")

__device__ __forceinline__ void ldm4(u32 &r0, u32 &r1, u32 &r2, u32 &r3, u32 addr) {
    asm volatile("ldmatrix.sync.aligned.m8n8.x4.shared.b16 {%0,%1,%2,%3}, [%4];"
                 : "=r"(r0), "=r"(r1), "=r"(r2), "=r"(r3) : "r"(addr));
}

// int8 IMMA: m16n8k32, s32 accumulate.
__device__ __forceinline__ void mma16832(int* d, u32 a0, u32 a1, u32 a2, u32 a3,
                                         u32 b0, u32 b1) {
    asm volatile("mma.sync.aligned.m16n8k32.row.col.s32.s8.s8.s32 "
                 "{%0,%1,%2,%3}, {%4,%5,%6,%7}, {%8,%9}, {%0,%1,%2,%3};"
                 : "+r"(d[0]), "+r"(d[1]), "+r"(d[2]), "+r"(d[3])
                 : "r"(a0), "r"(a1), "r"(a2), "r"(a3), "r"(b0), "r"(b1));
}

// packed fp32x2 FMA (even/odd K partial sums; zero precision loss)
__device__ __forceinline__ void fma2(ull &d, ull a, ull b) {
    asm("fma.rn.f32x2 %0, %1, %2, %3;" : "=l"(d) : "l"(a), "l"(b), "l"(d));
}
__device__ __forceinline__ float2 u2f2(ull v) {
    float2 r;
    r.x = __uint_as_float((unsigned)(v & 0xffffffffull));
    r.y = __uint_as_float((unsigned)(v >> 32));
    return r;
}

// =====================================================================
// Quantization kernels: per-row symmetric int8. One block (256 thr) per row.
// =====================================================================
__device__ __forceinline__ void quant_row(const float* src, int8_t* dst, float* scale_out) {
    __shared__ float wmax[8];
    const int tid = threadIdx.x;
    float4 v = ((const float4*)src)[tid];
    float m = fmaxf(fmaxf(fabsf(v.x), fabsf(v.y)), fmaxf(fabsf(v.z), fabsf(v.w)));
#pragma unroll
    for (int off = 16; off; off >>= 1)
        m = fmaxf(m, __shfl_xor_sync(0xffffffffu, m, off));
    if ((tid & 31) == 0) wmax[tid >> 5] = m;
    __syncthreads();
    float mm = wmax[0];
#pragma unroll
    for (int w = 1; w < 8; ++w) mm = fmaxf(mm, wmax[w]);
    float inv = (mm > 0.f) ? 127.0f / mm : 0.f;
    int a = __float2int_rn(v.x * inv), b = __float2int_rn(v.y * inv);
    int c = __float2int_rn(v.z * inv), d = __float2int_rn(v.w * inv);
    u32 p = (u32)(a & 255) | ((u32)(b & 255) << 8) | ((u32)(c & 255) << 16) | ((u32)(d & 255) << 24);
    ((u32*)dst)[tid] = p;
    if (tid == 0) *scale_out = (mm > 0.f) ? mm / 127.0f : 0.f;
}

__global__ __launch_bounds__(256)
void conv_q_kernel(const float* __restrict__ q) {
    int tok = blockIdx.x;
    quant_row(q + (size_t)tok * D_MODEL, g_qi8 + (size_t)tok * D_MODEL, &g_sq[tok]);
}

__global__ __launch_bounds__(256)
void conv_k_kernel(const float* __restrict__ Ks) {
    int row = blockIdx.x;   // lvl*SLOTS + slot
    quant_row(Ks + (size_t)row * D_MODEL, g_ki8 + (size_t)row * D_MODEL, &g_sk[row]);
}

// =====================================================================
// FUSED kernel: blocks [0,768)   = int8 IMMA scores + top-16 filter
//               blocks [768,1792)= router hidden (fp32 FFMA2)
// Scores: CTA = 64-token tile; 4-stage cp.async pipeline, ONE sync per kc;
// top-16 scan split across 128 threads (2/token), ordered merge at end.
// =====================================================================
#define N_SCORE_BLK (LEVELS * NTOK / 64)          // 768
#define N_ROUTER_BLK ((NTOK / 64) * (HDIM / 128)) // 1024

// scores smem layout (dynamic)
#define SM_A   0                        // [4][64 rows][64 B]   = 16 KB
#define SM_B   16384                    // [4][128 rows][64 B]  = 32 KB
#define SM_S   49152                    // float [64][129]      = 33024 B
#define SM_SAL (SM_S + 64 * 129 * 4)    // float [128]
#define SM_SK  (SM_SAL + 512)           // float [128]
#define SM_SQ  (SM_SK + 512)            // float [64]
#define FUSED_SMEM (SM_SQ + 512)

__device__ __forceinline__ void scores_block(char* dsm, int bid, const float* sal) {
    u32 smb;
    asm("{ .reg .u64 t; cvta.to.shared.u64 t, %1; cvt.u32.u64 %0, t; }" : "=r"(smb) : "l"(dsm));

    const int tid  = threadIdx.x;
    const int lane = tid & 31;
    const int wn   = tid >> 5;             // 0..7, 16 slots each
    const int lvl   = bid >> 8;            // 256 token-tiles per level
    const int ttile = bid & 255;

    const char* qg = (const char*)g_qi8 + (size_t)ttile * 64 * 1024;
    const char* kg = (const char*)g_ki8 + (size_t)lvl * SLOTS * 1024;

    float* sS   = (float*)(dsm + SM_S);
    float* sSal = (float*)(dsm + SM_SAL);
    float* sSk  = (float*)(dsm + SM_SK);
    float* sSq  = (float*)(dsm + SM_SQ);

    if (tid < 64) sSq[tid] = g_sq[ttile * 64 + tid];

    // one flat iteration index: it = st*16 + kc, buffer = it & 3
    auto issue = [&](int it) {
        const int st = it >> 4, kc = it & 15, buf = it & 3;
        const int kb = kc * 64;
        {
            int row = tid >> 2, c = tid & 3;
            u32 sw = (u32)(((c ^ (row & 3)) << 4) + row * 64);
            cp16(smb + SM_A + buf * 4096 + sw, qg + (size_t)row * 1024 + kb + c * 16);
        }
#pragma unroll
        for (int h = 0; h < 2; ++h) {
            int e = tid + 256 * h;
            int row = e >> 2, c = e & 3;
            u32 sw = (u32)(((c ^ (row & 3)) << 4) + row * 64);
            cp16(smb + SM_B + buf * 8192 + sw,
                 kg + (size_t)(st * 128 + row) * 1024 + kb + c * 16);
        }
    };

    int acc[4][2][4];
    float tv[CAND]; int ti[CAND];
#pragma unroll
    for (int k = 0; k < CAND; ++k) { tv[k] = -INFINITY; ti[k] = 0; }

    // prologue: 3 stages in flight (one commit-group each)
    issue(0); CP_COMMIT();
    issue(1); CP_COMMIT();
    issue(2); CP_COMMIT();

    const int stok  = tid & 63;            // scan token (tid < 128)
    const int shalf = (tid >> 6) & 1;      // scan half: slots [shalf*64, +64)

    for (int st = 0; st < 32; ++st) {
#pragma unroll
        for (int i = 0; i < 4; ++i)
#pragma unroll
            for (int j = 0; j < 2; ++j)
#pragma unroll
                for (int r = 0; r < 4; ++r) acc[i][j][r] = 0;

        for (int kc = 0; kc < 16; ++kc) {
            const int it  = st * 16 + kc;
            const int buf = it & 3;
            // every loop iter commits exactly one group (maybe empty), so
            // data for iter `it` is always safe after wait_group 2.
            CP_WAIT2();
            __syncthreads();
            if (it + 3 < 512) issue(it + 3);
            CP_COMMIT();

            const u32 aB = smb + SM_A + buf * 4096;
            const u32 bB = smb + SM_B + buf * 8192;
            const int mid = lane >> 3, lr = lane & 7;
#pragma unroll
            for (int s = 0; s < 2; ++s) {
                const int c0 = s * 2;        // 32 int8 of k per step
                u32 a[4][4];
#pragma unroll
                for (int i = 0; i < 4; ++i) {
                    int row = i * 16 + (mid & 1) * 8 + lr;
                    int ch  = c0 + (mid >> 1);
                    ldm4(a[i][0], a[i][1], a[i][2], a[i][3],
                         aB + row * 64 + ((ch ^ (row & 3)) << 4));
                }
                u32 b[4];
                {
                    int slot = wn * 16 + (mid >> 1) * 8 + lr;
                    int ch   = c0 + (mid & 1);
                    ldm4(b[0], b[1], b[2], b[3],
                         bB + slot * 64 + ((ch ^ (slot & 3)) << 4));
                }
#pragma unroll
                for (int i = 0; i < 4; ++i)
#pragma unroll
                    for (int j = 0; j < 2; ++j)
                        mma16832(acc[i][j], a[i][0], a[i][1], a[i][2], a[i][3],
                                 b[j * 2], b[j * 2 + 1]);
            }
        }
        __syncthreads();   // all MMAs of this tile done before staging scores

        // ---- epilogue: stage scaled scores, split top-16 scan ----
        if (tid < 128) {
            sSal[tid] = sal[lvl * SLOTS + st * 128 + tid];
            sSk[tid]  = g_sk[lvl * SLOTS + st * 128 + tid];
        }
#pragma unroll
        for (int i = 0; i < 4; ++i) {
            int r0 = i * 16 + (lane >> 2);
            float s0 = sSq[r0] * 0.03125f;
            float s1 = sSq[r0 + 8] * 0.03125f;
#pragma unroll
            for (int j = 0; j < 2; ++j) {
                int col = wn * 16 + j * 8 + (lane & 3) * 2;
                sS[r0 * 129 + col]           = (float)acc[i][j][0] * s0;
                sS[r0 * 129 + col + 1]       = (float)acc[i][j][1] * s0;
                sS[(r0 + 8) * 129 + col]     = (float)acc[i][j][2] * s1;
                sS[(r0 + 8) * 129 + col + 1] = (float)acc[i][j][3] * s1;
            }
        }
        __syncthreads();

        if (tid < 128) {
            const float* rowS = sS + stok * 129 + shalf * 64;
            const float* salp = sSal + shalf * 64;
            const float* skp  = sSk  + shalf * 64;
            const int slot0 = st * 128 + shalf * 64;
#pragma unroll 4
            for (int s = 0; s < 64; ++s) {
                float v = fmaf(rowS[s], skp[s], salp[s]);
                if (v > tv[CAND - 1]) {
                    tv[CAND - 1] = v; ti[CAND - 1] = slot0 + s;
#pragma unroll
                    for (int k = CAND - 1; k > 0; --k) {
                        if (tv[k] > tv[k - 1]) {
                            float a = tv[k]; tv[k] = tv[k - 1]; tv[k - 1] = a;
                            int   b = ti[k]; ti[k] = ti[k - 1]; ti[k - 1] = b;
                        }
                    }
                }
            }
        }
        __syncthreads();
    }

    // ---- final: merge each token's two half-lists (ordered, tie -> lower slot) ----
    float* mv = sS;                       // 128 * 16 floats
    int*   mi = (int*)(sS + 128 * 16);    // 128 * 16 ints
    if (tid < 128) {
#pragma unroll
        for (int k = 0; k < CAND; ++k) { mv[tid * 16 + k] = tv[k]; mi[tid * 16 + k] = ti[k]; }
    }
    __syncthreads();
    if (tid < 64) {
        float bv[CAND]; int bi[CAND];
#pragma unroll
        for (int k = 0; k < CAND; ++k) {
            bv[k] = mv[(tid + 64) * 16 + k];
            bi[k] = mi[(tid + 64) * 16 + k];
        }
        int tok = ttile * 64 + tid;
        size_t cb = ((size_t)lvl * NTOK + tok) * CAND;
        int ia = 0, ib = 0;
#pragma unroll
        for (int k = 0; k < CAND; ++k) {
            bool pickA;
            if (ia >= CAND)      pickA = false;
            else if (ib >= CAND) pickA = true;
            else pickA = (tv[ia] > bv[ib]) || (tv[ia] == bv[ib] && ti[ia] < bi[ib]);
            g_ci[cb + k] = pickA ? ti[ia] : bi[ib];
            if (pickA) ++ia; else ++ib;
        }
    }
}

// router hidden h = relu(q @ W1 + b1). fp32 via FFMA2 (precision-critical).
__device__ __forceinline__ void router_block(char* dsm, int bid2,
                                             const float* __restrict__ q,
                                             const float* __restrict__ W1,
                                             const float* __restrict__ b1) {
    ull* qs = (ull*)dsm;             // 64*8 entries = 4 KB
    ull* bs = (ull*)(dsm + 4096);    // 8*128 entries = 8 KB

    const int tid = threadIdx.x;
    const int tx = tid & 15;
    const int ty = tid >> 4;
    const int tok0 = (bid2 & 255) * 64;
    const int n0   = (bid2 >> 8) * 128;

    const float* qbase = q + (size_t)tok0 * D_MODEL;
    const int l_r  = tid >> 3;
    const int l_kp = tid & 7;

    ull acc[4][8];
#pragma unroll
    for (int j = 0; j < 4; ++j)
#pragma unroll
        for (int i = 0; i < 8; ++i) acc[j][i] = 0ull;

    float2 pq[2];
    float  pb[8];
#pragma unroll
    for (int j = 0; j < 2; ++j)
        pq[j] = *(const float2*)(qbase + (size_t)(l_r + 32 * j) * D_MODEL + 2 * l_kp);
#pragma unroll
    for (int i = 0; i < 8; ++i) {
        int e = tid + 256 * i;
        int k = e >> 7, nl = e & 127;
        pb[i] = W1[(size_t)k * HDIM + n0 + nl];
    }

    for (int kc = 0; kc < D_MODEL / 16; ++kc) {
        __syncthreads();
#pragma unroll
        for (int j = 0; j < 2; ++j)
            ((float2*)qs)[(l_r + 32 * j) * 8 + l_kp] = pq[j];
#pragma unroll
        for (int i = 0; i < 8; ++i) {
            int e = tid + 256 * i;
            int k = e >> 7, nl = e & 127;
            int kp = k >> 1, par = k & 1;
            ((float*)bs)[(kp * 128 + (nl ^ (kp << 2))) * 2 + par] = pb[i];
        }
        __syncthreads();

        if (kc + 1 < D_MODEL / 16) {
            const int kb = (kc + 1) * 16;
#pragma unroll
            for (int j = 0; j < 2; ++j)
                pq[j] = *(const float2*)(qbase + (size_t)(l_r + 32 * j) * D_MODEL + kb + 2 * l_kp);
#pragma unroll
            for (int i = 0; i < 8; ++i) {
                int e = tid + 256 * i;
                int k = e >> 7, nl = e & 127;
                pb[i] = W1[(size_t)(kb + k) * HDIM + n0 + nl];
            }
        }

#pragma unroll
        for (int kp = 0; kp < 8; ++kp) {
            ull qq0 = qs[(ty +  0) * 8 + kp];
            ull qq1 = qs[(ty + 16) * 8 + kp];
            ull qq2 = qs[(ty + 32) * 8 + kp];
            ull qq3 = qs[(ty + 48) * 8 + kp];
#pragma unroll
            for (int i = 0; i < 8; ++i) {
                ull kk = bs[kp * 128 + ((tx + 16 * i) ^ (kp << 2))];
                fma2(acc[0][i], qq0, kk);
                fma2(acc[1][i], qq1, kk);
                fma2(acc[2][i], qq2, kk);
                fma2(acc[3][i], qq3, kk);
            }
        }
    }

#pragma unroll
    for (int j = 0; j < 4; ++j)
#pragma unroll
        for (int i = 0; i < 8; ++i) {
            int t = ty + 16 * j;
            int n = tx + 16 * i;
            float2 a = u2f2(acc[j][i]);
            float v = a.x + a.y + b1[n0 + n];
            g_h[(size_t)(tok0 + t) * HDIM + n0 + n] = fmaxf(v, 0.0f);
        }
}

__global__ __launch_bounds__(256, 2)
void fused_scores_router_kernel(const float* __restrict__ sal,
                                const float* __restrict__ q,
                                const float* __restrict__ W1,
                                const float* __restrict__ b1) {
    extern __shared__ char dsm[];
    const int bid = blockIdx.x;
    if (bid < N_SCORE_BLK) scores_block(dsm, bid, sal);
    else                   router_block(dsm, bid - N_SCORE_BLK, q, W1, b1);
}

// =====================================================================
// Route weights = softmax(h @ W2 + b2). One warp per token.
// =====================================================================
__global__ void route_kernel(const float* __restrict__ W2,
                             const float* __restrict__ b2)
{
    int gw = (blockIdx.x * blockDim.x + threadIdx.x) >> 5;
    int lane = threadIdx.x & 31;
    if (gw >= NTOK) return;

    const float* hr = g_h + (size_t)gw * HDIM;
    float a0 = 0.f, a1 = 0.f, a2 = 0.f;
    for (int i = lane; i < HDIM; i += 32) {
        float hv = hr[i];
        a0 = fmaf(hv, W2[i * 3 + 0], a0);
        a1 = fmaf(hv, W2[i * 3 + 1], a1);
        a2 = fmaf(hv, W2[i * 3 + 2], a2);
    }
#pragma unroll
    for (int off = 16; off; off >>= 1) {
        a0 += __shfl_down_sync(0xffffffffu, a0, off);
        a1 += __shfl_down_sync(0xffffffffu, a1, off);
        a2 += __shfl_down_sync(0xffffffffu, a2, off);
    }
    if (lane == 0) {
        a0 += b2[0]; a1 += b2[1]; a2 += b2[2];
        float m = fmaxf(a0, fmaxf(a1, a2));
        float e0 = expf(a0 - m), e1 = expf(a1 - m), e2 = expf(a2 - m);
        float inv = 1.0f / (e0 + e1 + e2);
        g_route[gw * 3 + 0] = e0 * inv;
        g_route[gw * 3 + 1] = e1 * inv;
        g_route[gw * 3 + 2] = e2 * inv;
    }
}

// =====================================================================
// Rescore candidates exactly in fp32, top-8-of-16 (jax tie-break: lower
// slot first), softmax, route-weighted V gather, sum levels -> output.
// One block per token, 256 threads.
// =====================================================================
__global__ __launch_bounds__(256)
void rescore_out_kernel(const float* __restrict__ q,
                        const float* __restrict__ Ks,
                        const float* __restrict__ Vs,
                        const float* __restrict__ sal,
                        float* __restrict__ out)
{
    __shared__ float qs[D_MODEL];
    __shared__ float csc[LEVELS][CAND];
    __shared__ int   csl[LEVELS][CAND];
    __shared__ float w8[LEVELS][TOPK];
    __shared__ int   i8[LEVELS][TOPK];

    const int tok = blockIdx.x;
    const int tid = threadIdx.x;
    ((float4*)qs)[tid] = ((const float4*)(q + (size_t)tok * D_MODEL))[tid];
    if (tid < LEVELS * CAND) {
        int l = tid / CAND, c = tid % CAND;
        csl[l][c] = g_ci[((size_t)l * NTOK + tok) * CAND + c];
    }
    __syncthreads();

    const int w = tid >> 5, lane = tid & 31;
    for (int d = w; d < LEVELS * CAND; d += 8) {
        int l = d / CAND, c = d % CAND;
        int slot = csl[l][c];
        const float* kr = Ks + ((size_t)l * SLOTS + slot) * D_MODEL;
        float acc = 0.f;
#pragma unroll
        for (int i = 0; i < 8; ++i) {
            int o = lane * 4 + i * 128;
            float4 kv = *(const float4*)(kr + o);
            float4 qv = *(const float4*)(qs + o);
            acc = fmaf(qv.x, kv.x, acc); acc = fmaf(qv.y, kv.y, acc);
            acc = fmaf(qv.z, kv.z, acc); acc = fmaf(qv.w, kv.w, acc);
        }
#pragma unroll
        for (int off = 16; off; off >>= 1) acc += __shfl_down_sync(0xffffffffu, acc, off);
        if (lane == 0) csc[l][c] = fmaf(acc, 0.03125f, __ldg(&sal[l * SLOTS + slot]));
    }
    __syncthreads();

    if (tid < LEVELS) {
        int l = tid;
        float lv[CAND]; int li[CAND];
#pragma unroll
        for (int c = 0; c < CAND; ++c) { lv[c] = csc[l][c]; li[c] = csl[l][c]; }
        float sv[TOPK]; int si[TOPK];
#pragma unroll
        for (int k = 0; k < TOPK; ++k) {
            int bj = 0;
#pragma unroll
            for (int c = 1; c < CAND; ++c) {
                bool better = (lv[c] > lv[bj]) || (lv[c] == lv[bj] && li[c] < li[bj]);
                if (better) bj = c;
            }
            sv[k] = lv[bj]; si[k] = li[bj]; lv[bj] = -INFINITY;
        }
        float m = sv[0];
#pragma unroll
        for (int k = 1; k < TOPK; ++k) m = fmaxf(m, sv[k]);
        float sum = 0.f, e[TOPK];
#pragma unroll
        for (int k = 0; k < TOPK; ++k) { e[k] = expf(sv[k] - m); sum += e[k]; }
        float sc = g_route[tok * 3 + l] / sum;
#pragma unroll
        for (int k = 0; k < TOPK; ++k) { w8[l][k] = e[k] * sc; i8[l][k] = si[k]; }
    }
    __syncthreads();

    float4 o = make_float4(0.f, 0.f, 0.f, 0.f);
#pragma unroll
    for (int l = 0; l < LEVELS; ++l) {
#pragma unroll
        for (int k = 0; k < TOPK; ++k) {
            float ww = w8[l][k];
            const float4* vr = (const float4*)(Vs + ((size_t)l * SLOTS + i8[l][k]) * D_MODEL) + tid;
            float4 vv = *vr;
            o.x = fmaf(ww, vv.x, o.x); o.y = fmaf(ww, vv.y, o.y);
            o.z = fmaf(ww, vv.z, o.z); o.w = fmaf(ww, vv.w, o.w);
        }
    }
    ((float4*)(out + (size_t)tok * D_MODEL))[tid] = o;
}

// =====================================================================
extern "C" void kernel_launch(void* const* d_in, const int* in_sizes, int n_in,
                              void* d_out, int out_size)
{
    (void)in_sizes; (void)n_in; (void)out_size;
    const float* q    = (const float*)d_in[0];
    const float* Ksm  = (const float*)d_in[1];
    const float* Vsm  = (const float*)d_in[2];
    const float* sal  = (const float*)d_in[3];
    const float* W1   = (const float*)d_in[4];
    const float* b1   = (const float*)d_in[5];
    const float* W2   = (const float*)d_in[6];
    const float* b2   = (const float*)d_in[7];
    float* out = (float*)d_out;

    cudaFuncSetAttribute(fused_scores_router_kernel,
                         cudaFuncAttributeMaxDynamicSharedMemorySize, FUSED_SMEM);

    conv_q_kernel<<<NTOK, 256>>>(q);
    conv_k_kernel<<<LEVELS * SLOTS, 256>>>(Ksm);
    fused_scores_router_kernel<<<N_SCORE_BLK + N_ROUTER_BLK, 256, FUSED_SMEM>>>(sal, q, W1, b1);
    route_kernel<<<NTOK / 4, 128>>>(W2, b2);
    rescore_out_kernel<<<NTOK, 256>>>(q, Ksm, Vsm, sal, out);
}

// round 10
// speedup vs baseline: 1.3090x; 1.3090x over previous
#include <cuda_runtime.h>
#include <cuda_bf16.h>
#include <math.h>
#include <stdint.h>

#define D_MODEL 1024
#define HDIM    512
#define SLOTS   4096
#define LEVELS  3
#define NTOK    16384
#define TOPK    8
#define CAND    16

typedef unsigned long long ull;
typedef unsigned int u32;

// ---------------- scratch (static __device__, no allocations) ----------------
__device__ int8_t g_qi8[(size_t)NTOK * D_MODEL];                  // 16 MB int8 q
__device__ int8_t g_ki8[(size_t)LEVELS * SLOTS * D_MODEL];        // 12 MB int8 K
__device__ float  g_sq[NTOK];                                     // per-token scale
__device__ float  g_sk[LEVELS * SLOTS];                           // per-slot scale
__device__ float  g_h[(size_t)NTOK * HDIM];                       // router hidden
__device__ float  g_route[NTOK * LEVELS];                         // route weights
__device__ int    g_ci[(size_t)LEVELS * NTOK * CAND];             // top-16 candidates

// ---------------- PTX helpers (baseline-ISA only) ----------------
__device__ __forceinline__ void cp16(u32 dst, const void* src) {
    asm volatile("cp.async.cg.shared.global [%0], [%1], 16;" :: "r"(dst), "l"(src) : "memory");
}
#define CP_COMMIT() asm volatile("cp.async.commit_group;" ::: "memory")
#define CP_WAIT2()  asm volatile("cp.async.wait_group 2;" ::: "memory")

__device__ __forceinline__ void ldm4(u32 &r0, u32 &r1, u32 &r2, u32 &r3, u32 addr) {
    asm volatile("ldmatrix.sync.aligned.m8n8.x4.shared.b16 {%0,%1,%2,%3}, [%4];"
                 : "=r"(r0), "=r"(r1), "=r"(r2), "=r"(r3) : "r"(addr));
}

// int8 IMMA: m16n8k32, s32 accumulate.
__device__ __forceinline__ void mma16832(int* d, u32 a0, u32 a1, u32 a2, u32 a3,
                                         u32 b0, u32 b1) {
    asm volatile("mma.sync.aligned.m16n8k32.row.col.s32.s8.s8.s32 "
                 "{%0,%1,%2,%3}, {%4,%5,%6,%7}, {%8,%9}, {%0,%1,%2,%3};"
                 : "+r"(d[0]), "+r"(d[1]), "+r"(d[2]), "+r"(d[3])
                 : "r"(a0), "r"(a1), "r"(a2), "r"(a3), "r"(b0), "r"(b1));
}

// packed fp32x2 FMA (even/odd K partial sums; zero precision loss)
__device__ __forceinline__ void fma2(ull &d, ull a, ull b) {
    asm("fma.rn.f32x2 %0, %1, %2, %3;" : "=l"(d) : "l"(a), "l"(b), "l"(d));
}
__device__ __forceinline__ float2 u2f2(ull v) {
    float2 r;
    r.x = __uint_as_float((unsigned)(v & 0xffffffffull));
    r.y = __uint_as_float((unsigned)(v >> 32));
    return r;
}

// =====================================================================
// Quantization: per-row symmetric int8, one block (256 thr) per row.
// Single kernel covers q rows [0,NTOK) then K rows [NTOK, NTOK+3*SLOTS).
// =====================================================================
__device__ __forceinline__ void quant_row(const float* src, int8_t* dst, float* scale_out) {
    __shared__ float wmax[8];
    const int tid = threadIdx.x;
    float4 v = ((const float4*)src)[tid];
    float m = fmaxf(fmaxf(fabsf(v.x), fabsf(v.y)), fmaxf(fabsf(v.z), fabsf(v.w)));
#pragma unroll
    for (int off = 16; off; off >>= 1)
        m = fmaxf(m, __shfl_xor_sync(0xffffffffu, m, off));
    if ((tid & 31) == 0) wmax[tid >> 5] = m;
    __syncthreads();
    float mm = wmax[0];
#pragma unroll
    for (int w = 1; w < 8; ++w) mm = fmaxf(mm, wmax[w]);
    float inv = (mm > 0.f) ? 127.0f / mm : 0.f;
    int a = __float2int_rn(v.x * inv), b = __float2int_rn(v.y * inv);
    int c = __float2int_rn(v.z * inv), d = __float2int_rn(v.w * inv);
    u32 p = (u32)(a & 255) | ((u32)(b & 255) << 8) | ((u32)(c & 255) << 16) | ((u32)(d & 255) << 24);
    ((u32*)dst)[tid] = p;
    if (tid == 0) *scale_out = (mm > 0.f) ? mm / 127.0f : 0.f;
}

__global__ __launch_bounds__(256)
void conv_kernel(const float* __restrict__ q, const float* __restrict__ Ks) {
    int row = blockIdx.x;
    if (row < NTOK) {
        quant_row(q + (size_t)row * D_MODEL, g_qi8 + (size_t)row * D_MODEL, &g_sq[row]);
    } else {
        int r = row - NTOK;   // lvl*SLOTS + slot
        quant_row(Ks + (size_t)r * D_MODEL, g_ki8 + (size_t)r * D_MODEL, &g_sk[r]);
    }
}

// =====================================================================
// FUSED kernel: blocks [0,768)   = int8 IMMA scores + top-16 filter
//               blocks [768,1792)= router hidden (fp32 FFMA2)
// Scores: CTA = 64-token tile; 4-buffer cp.async ring, prefetch distance 2,
// round-8 barrier structure (issue -> commit -> wait -> sync -> mma -> sync).
// =====================================================================
#define N_SCORE_BLK (LEVELS * NTOK / 64)          // 768
#define N_ROUTER_BLK ((NTOK / 64) * (HDIM / 128)) // 1024

// scores smem layout (dynamic)
#define SM_A   0                        // [4][64 rows][64 B]   = 16 KB
#define SM_B   16384                    // [4][128 rows][64 B]  = 32 KB
#define SM_S   49152                    // float [64][129]      = 33024 B
#define SM_SAL (SM_S + 64 * 129 * 4)    // float [128]
#define SM_SK  (SM_SAL + 512)           // float [128]
#define SM_SQ  (SM_SK + 512)            // float [64]
#define FUSED_SMEM (SM_SQ + 512)

__device__ __forceinline__ void scores_block(char* dsm, int bid, const float* sal) {
    u32 smb;
    asm("{ .reg .u64 t; cvta.to.shared.u64 t, %1; cvt.u32.u64 %0, t; }" : "=r"(smb) : "l"(dsm));

    const int tid  = threadIdx.x;
    const int lane = tid & 31;
    const int wn   = tid >> 5;             // 0..7, 16 slots each
    const int lvl   = bid >> 8;            // 256 token-tiles per level
    const int ttile = bid & 255;

    const char* qg = (const char*)g_qi8 + (size_t)ttile * 64 * 1024;
    const char* kg = (const char*)g_ki8 + (size_t)lvl * SLOTS * 1024;

    float* sS   = (float*)(dsm + SM_S);
    float* sSal = (float*)(dsm + SM_SAL);
    float* sSk  = (float*)(dsm + SM_SK);
    float* sSq  = (float*)(dsm + SM_SQ);

    if (tid < 64) sSq[tid] = g_sq[ttile * 64 + tid];

    // flat iteration index: it = st*16 + kc, buffer = it & 3
    auto issue = [&](int it) {
        const int st = it >> 4, kc = it & 15, buf = it & 3;
        const int kb = kc * 64;
        {
            int row = tid >> 2, c = tid & 3;
            u32 sw = (u32)(((c ^ (row & 3)) << 4) + row * 64);
            cp16(smb + SM_A + buf * 4096 + sw, qg + (size_t)row * 1024 + kb + c * 16);
        }
#pragma unroll
        for (int h = 0; h < 2; ++h) {
            int e = tid + 256 * h;
            int row = e >> 2, c = e & 3;
            u32 sw = (u32)(((c ^ (row & 3)) << 4) + row * 64);
            cp16(smb + SM_B + buf * 8192 + sw,
                 kg + (size_t)(st * 128 + row) * 1024 + kb + c * 16);
        }
    };

    int acc[4][2][4];
    float tv[CAND]; int ti[CAND];
#pragma unroll
    for (int k = 0; k < CAND; ++k) { tv[k] = -INFINITY; ti[k] = 0; }

    // prologue: 2 stages in flight
    issue(0); CP_COMMIT();
    issue(1); CP_COMMIT();

    for (int st = 0; st < 32; ++st) {
#pragma unroll
        for (int i = 0; i < 4; ++i)
#pragma unroll
            for (int j = 0; j < 2; ++j)
#pragma unroll
                for (int r = 0; r < 4; ++r) acc[i][j][r] = 0;

        for (int kc = 0; kc < 16; ++kc) {
            const int it  = st * 16 + kc;
            const int buf = it & 3;
            if (it + 2 < 512) issue(it + 2);
            CP_COMMIT();               // one group per iter (maybe empty)
            CP_WAIT2();                // groups it+1, it+2 may pend; it is done
            __syncthreads();

            const u32 aB = smb + SM_A + buf * 4096;
            const u32 bB = smb + SM_B + buf * 8192;
            const int mid = lane >> 3, lr = lane & 7;
#pragma unroll
            for (int s = 0; s < 2; ++s) {
                const int c0 = s * 2;        // 32 int8 of k per step
                u32 a[4][4];
#pragma unroll
                for (int i = 0; i < 4; ++i) {
                    int row = i * 16 + (mid & 1) * 8 + lr;
                    int ch  = c0 + (mid >> 1);
                    ldm4(a[i][0], a[i][1], a[i][2], a[i][3],
                         aB + row * 64 + ((ch ^ (row & 3)) << 4));
                }
                u32 b[4];
                {
                    int slot = wn * 16 + (mid >> 1) * 8 + lr;
                    int ch   = c0 + (mid & 1);
                    ldm4(b[0], b[1], b[2], b[3],
                         bB + slot * 64 + ((ch ^ (slot & 3)) << 4));
                }
#pragma unroll
                for (int i = 0; i < 4; ++i)
#pragma unroll
                    for (int j = 0; j < 2; ++j)
                        mma16832(acc[i][j], a[i][0], a[i][1], a[i][2], a[i][3],
                                 b[j * 2], b[j * 2 + 1]);
            }
            __syncthreads();
        }

        // ---- epilogue: stage scaled scores, scan top-16 (proven round-8 path) ----
        if (tid < 128) {
            sSal[tid] = sal[lvl * SLOTS + st * 128 + tid];
            sSk[tid]  = g_sk[lvl * SLOTS + st * 128 + tid];
        }
#pragma unroll
        for (int i = 0; i < 4; ++i) {
            int r0 = i * 16 + (lane >> 2);
            float s0 = sSq[r0] * 0.03125f;
            float s1 = sSq[r0 + 8] * 0.03125f;
#pragma unroll
            for (int j = 0; j < 2; ++j) {
                int col = wn * 16 + j * 8 + (lane & 3) * 2;
                sS[r0 * 129 + col]           = (float)acc[i][j][0] * s0;
                sS[r0 * 129 + col + 1]       = (float)acc[i][j][1] * s0;
                sS[(r0 + 8) * 129 + col]     = (float)acc[i][j][2] * s1;
                sS[(r0 + 8) * 129 + col + 1] = (float)acc[i][j][3] * s1;
            }
        }
        __syncthreads();

        if (tid < 64) {
#pragma unroll 4
            for (int s = 0; s < 128; ++s) {
                float v = fmaf(sS[tid * 129 + s], sSk[s], sSal[s]);
                if (v > tv[CAND - 1]) {
                    tv[CAND - 1] = v; ti[CAND - 1] = st * 128 + s;
#pragma unroll
                    for (int k = CAND - 1; k > 0; --k) {
                        if (tv[k] > tv[k - 1]) {
                            float a = tv[k]; tv[k] = tv[k - 1]; tv[k - 1] = a;
                            int   b = ti[k]; ti[k] = ti[k - 1]; ti[k - 1] = b;
                        }
                    }
                }
            }
        }
        __syncthreads();
    }

    if (tid < 64) {
        int tok = ttile * 64 + tid;
        size_t cb = ((size_t)lvl * NTOK + tok) * CAND;
#pragma unroll
        for (int k = 0; k < CAND; ++k) g_ci[cb + k] = ti[k];
    }
}

// router hidden h = relu(q @ W1 + b1). fp32 via FFMA2 (precision-critical).
__device__ __forceinline__ void router_block(char* dsm, int bid2,
                                             const float* __restrict__ q,
                                             const float* __restrict__ W1,
                                             const float* __restrict__ b1) {
    ull* qs = (ull*)dsm;             // 64*8 entries = 4 KB
    ull* bs = (ull*)(dsm + 4096);    // 8*128 entries = 8 KB

    const int tid = threadIdx.x;
    const int tx = tid & 15;
    const int ty = tid >> 4;
    const int tok0 = (bid2 & 255) * 64;
    const int n0   = (bid2 >> 8) * 128;

    const float* qbase = q + (size_t)tok0 * D_MODEL;
    const int l_r  = tid >> 3;
    const int l_kp = tid & 7;

    ull acc[4][8];
#pragma unroll
    for (int j = 0; j < 4; ++j)
#pragma unroll
        for (int i = 0; i < 8; ++i) acc[j][i] = 0ull;

    float2 pq[2];
    float  pb[8];
#pragma unroll
    for (int j = 0; j < 2; ++j)
        pq[j] = *(const float2*)(qbase + (size_t)(l_r + 32 * j) * D_MODEL + 2 * l_kp);
#pragma unroll
    for (int i = 0; i < 8; ++i) {
        int e = tid + 256 * i;
        int k = e >> 7, nl = e & 127;
        pb[i] = W1[(size_t)k * HDIM + n0 + nl];
    }

    for (int kc = 0; kc < D_MODEL / 16; ++kc) {
        __syncthreads();
#pragma unroll
        for (int j = 0; j < 2; ++j)
            ((float2*)qs)[(l_r + 32 * j) * 8 + l_kp] = pq[j];
#pragma unroll
        for (int i = 0; i < 8; ++i) {
            int e = tid + 256 * i;
            int k = e >> 7, nl = e & 127;
            int kp = k >> 1, par = k & 1;
            ((float*)bs)[(kp * 128 + (nl ^ (kp << 2))) * 2 + par] = pb[i];
        }
        __syncthreads();

        if (kc + 1 < D_MODEL / 16) {
            const int kb = (kc + 1) * 16;
#pragma unroll
            for (int j = 0; j < 2; ++j)
                pq[j] = *(const float2*)(qbase + (size_t)(l_r + 32 * j) * D_MODEL + kb + 2 * l_kp);
#pragma unroll
            for (int i = 0; i < 8; ++i) {
                int e = tid + 256 * i;
                int k = e >> 7, nl = e & 127;
                pb[i] = W1[(size_t)(kb + k) * HDIM + n0 + nl];
            }
        }

#pragma unroll
        for (int kp = 0; kp < 8; ++kp) {
            ull qq0 = qs[(ty +  0) * 8 + kp];
            ull qq1 = qs[(ty + 16) * 8 + kp];
            ull qq2 = qs[(ty + 32) * 8 + kp];
            ull qq3 = qs[(ty + 48) * 8 + kp];
#pragma unroll
            for (int i = 0; i < 8; ++i) {
                ull kk = bs[kp * 128 + ((tx + 16 * i) ^ (kp << 2))];
                fma2(acc[0][i], qq0, kk);
                fma2(acc[1][i], qq1, kk);
                fma2(acc[2][i], qq2, kk);
                fma2(acc[3][i], qq3, kk);
            }
        }
    }

#pragma unroll
    for (int j = 0; j < 4; ++j)
#pragma unroll
        for (int i = 0; i < 8; ++i) {
            int t = ty + 16 * j;
            int n = tx + 16 * i;
            float2 a = u2f2(acc[j][i]);
            float v = a.x + a.y + b1[n0 + n];
            g_h[(size_t)(tok0 + t) * HDIM + n0 + n] = fmaxf(v, 0.0f);
        }
}

__global__ __launch_bounds__(256, 2)
void fused_scores_router_kernel(const float* __restrict__ sal,
                                const float* __restrict__ q,
                                const float* __restrict__ W1,
                                const float* __restrict__ b1) {
    extern __shared__ char dsm[];
    const int bid = blockIdx.x;
    if (bid < N_SCORE_BLK) scores_block(dsm, bid, sal);
    else                   router_block(dsm, bid - N_SCORE_BLK, q, W1, b1);
}

// =====================================================================
// Route weights = softmax(h @ W2 + b2). One warp per token.
// =====================================================================
__global__ void route_kernel(const float* __restrict__ W2,
                             const float* __restrict__ b2)
{
    int gw = (blockIdx.x * blockDim.x + threadIdx.x) >> 5;
    int lane = threadIdx.x & 31;
    if (gw >= NTOK) return;

    const float* hr = g_h + (size_t)gw * HDIM;
    float a0 = 0.f, a1 = 0.f, a2 = 0.f;
    for (int i = lane; i < HDIM; i += 32) {
        float hv = hr[i];
        a0 = fmaf(hv, W2[i * 3 + 0], a0);
        a1 = fmaf(hv, W2[i * 3 + 1], a1);
        a2 = fmaf(hv, W2[i * 3 + 2], a2);
    }
#pragma unroll
    for (int off = 16; off; off >>= 1) {
        a0 += __shfl_down_sync(0xffffffffu, a0, off);
        a1 += __shfl_down_sync(0xffffffffu, a1, off);
        a2 += __shfl_down_sync(0xffffffffu, a2, off);
    }
    if (lane == 0) {
        a0 += b2[0]; a1 += b2[1]; a2 += b2[2];
        float m = fmaxf(a0, fmaxf(a1, a2));
        float e0 = expf(a0 - m), e1 = expf(a1 - m), e2 = expf(a2 - m);
        float inv = 1.0f / (e0 + e1 + e2);
        g_route[gw * 3 + 0] = e0 * inv;
        g_route[gw * 3 + 1] = e1 * inv;
        g_route[gw * 3 + 2] = e2 * inv;
    }
}

// =====================================================================
// Rescore candidates exactly in fp32, top-8-of-16 (jax tie-break: lower
// slot first), softmax, route-weighted V gather, sum levels -> output.
// One block per token, 256 threads.
// =====================================================================
__global__ __launch_bounds__(256)
void rescore_out_kernel(const float* __restrict__ q,
                        const float* __restrict__ Ks,
                        const float* __restrict__ Vs,
                        const float* __restrict__ sal,
                        float* __restrict__ out)
{
    __shared__ float qs[D_MODEL];
    __shared__ float csc[LEVELS][CAND];
    __shared__ int   csl[LEVELS][CAND];
    __shared__ float w8[LEVELS][TOPK];
    __shared__ int   i8[LEVELS][TOPK];

    const int tok = blockIdx.x;
    const int tid = threadIdx.x;
    ((float4*)qs)[tid] = ((const float4*)(q + (size_t)tok * D_MODEL))[tid];
    if (tid < LEVELS * CAND) {
        int l = tid / CAND, c = tid % CAND;
        csl[l][c] = g_ci[((size_t)l * NTOK + tok) * CAND + c];
    }
    __syncthreads();

    const int w = tid >> 5, lane = tid & 31;
    for (int d = w; d < LEVELS * CAND; d += 8) {
        int l = d / CAND, c = d % CAND;
        int slot = csl[l][c];
        const float* kr = Ks + ((size_t)l * SLOTS + slot) * D_MODEL;
        float acc = 0.f;
#pragma unroll
        for (int i = 0; i < 8; ++i) {
            int o = lane * 4 + i * 128;
            float4 kv = *(const float4*)(kr + o);
            float4 qv = *(const float4*)(qs + o);
            acc = fmaf(qv.x, kv.x, acc); acc = fmaf(qv.y, kv.y, acc);
            acc = fmaf(qv.z, kv.z, acc); acc = fmaf(qv.w, kv.w, acc);
        }
#pragma unroll
        for (int off = 16; off; off >>= 1) acc += __shfl_down_sync(0xffffffffu, acc, off);
        if (lane == 0) csc[l][c] = fmaf(acc, 0.03125f, __ldg(&sal[l * SLOTS + slot]));
    }
    __syncthreads();

    if (tid < LEVELS) {
        int l = tid;
        float lv[CAND]; int li[CAND];
#pragma unroll
        for (int c = 0; c < CAND; ++c) { lv[c] = csc[l][c]; li[c] = csl[l][c]; }
        float sv[TOPK]; int si[TOPK];
#pragma unroll
        for (int k = 0; k < TOPK; ++k) {
            int bj = 0;
#pragma unroll
            for (int c = 1; c < CAND; ++c) {
                bool better = (lv[c] > lv[bj]) || (lv[c] == lv[bj] && li[c] < li[bj]);
                if (better) bj = c;
            }
            sv[k] = lv[bj]; si[k] = li[bj]; lv[bj] = -INFINITY;
        }
        float m = sv[0];
#pragma unroll
        for (int k = 1; k < TOPK; ++k) m = fmaxf(m, sv[k]);
        float sum = 0.f, e[TOPK];
#pragma unroll
        for (int k = 0; k < TOPK; ++k) { e[k] = expf(sv[k] - m); sum += e[k]; }
        float sc = g_route[tok * 3 + l] / sum;
#pragma unroll
        for (int k = 0; k < TOPK; ++k) { w8[l][k] = e[k] * sc; i8[l][k] = si[k]; }
    }
    __syncthreads();

    float4 o = make_float4(0.f, 0.f, 0.f, 0.f);
#pragma unroll
    for (int l = 0; l < LEVELS; ++l) {
#pragma unroll
        for (int k = 0; k < TOPK; ++k) {
            float ww = w8[l][k];
            const float4* vr = (const float4*)(Vs + ((size_t)l * SLOTS + i8[l][k]) * D_MODEL) + tid;
            float4 vv = *vr;
            o.x = fmaf(ww, vv.x, o.x); o.y = fmaf(ww, vv.y, o.y);
            o.z = fmaf(ww, vv.z, o.z); o.w = fmaf(ww, vv.w, o.w);
        }
    }
    ((float4*)(out + (size_t)tok * D_MODEL))[tid] = o;
}

// =====================================================================
extern "C" void kernel_launch(void* const* d_in, const int* in_sizes, int n_in,
                              void* d_out, int out_size)
{
    (void)in_sizes; (void)n_in; (void)out_size;
    const float* q    = (const float*)d_in[0];
    const float* Ksm  = (const float*)d_in[1];
    const float* Vsm  = (const float*)d_in[2];
    const float* sal  = (const float*)d_in[3];
    const float* W1   = (const float*)d_in[4];
    const float* b1   = (const float*)d_in[5];
    const float* W2   = (const float*)d_in[6];
    const float* b2   = (const float*)d_in[7];
    float* out = (float*)d_out;

    cudaFuncSetAttribute(fused_scores_router_kernel,
                         cudaFuncAttributeMaxDynamicSharedMemorySize, FUSED_SMEM);

    conv_kernel<<<NTOK + LEVELS * SLOTS, 256>>>(q, Ksm);
    fused_scores_router_kernel<<<N_SCORE_BLK + N_ROUTER_BLK, 256, FUSED_SMEM>>>(sal, q, W1, b1);
    route_kernel<<<NTOK / 4, 128>>>(W2, b2);
    rescore_out_kernel<<<NTOK, 256>>>(q, Ksm, Vsm, sal, out);
}

// round 11
// speedup vs baseline: 1.3258x; 1.0128x over previous
#include <cuda_runtime.h>
#include <cuda_bf16.h>
#include <math.h>
#include <stdint.h>

#define D_MODEL 1024
#define HDIM    512
#define SLOTS   4096
#define LEVELS  3
#define NTOK    16384
#define TOPK    8
#define CAND    16

typedef unsigned long long ull;
typedef unsigned int u32;

// ---------------- scratch (static __device__, no allocations) ----------------
__device__ int8_t g_qi8[(size_t)NTOK * D_MODEL];                  // 16 MB int8 q
__device__ int8_t g_ki8[(size_t)LEVELS * SLOTS * D_MODEL];        // 12 MB int8 K
__device__ float  g_sq[NTOK];                                     // per-token scale
__device__ float  g_sk[LEVELS * SLOTS];                           // per-slot scale
__device__ float  g_h[(size_t)NTOK * HDIM];                       // router hidden
__device__ float  g_route[NTOK * LEVELS];                         // route weights
__device__ int    g_ci[(size_t)LEVELS * NTOK * CAND];             // top-16 candidates

// ---------------- PTX helpers (baseline-ISA only) ----------------
__device__ __forceinline__ void cp16(u32 dst, const void* src) {
    asm volatile("cp.async.cg.shared.global [%0], [%1], 16;" :: "r"(dst), "l"(src) : "memory");
}
#define CP_COMMIT() asm volatile("cp.async.commit_group;" ::: "memory")
#define CP_WAIT1()  asm volatile("cp.async.wait_group 1;" ::: "memory")
#define CP_WAIT0()  asm volatile("cp.async.wait_group 0;" ::: "memory")

__device__ __forceinline__ void ldm4(u32 &r0, u32 &r1, u32 &r2, u32 &r3, u32 addr) {
    asm volatile("ldmatrix.sync.aligned.m8n8.x4.shared.b16 {%0,%1,%2,%3}, [%4];"
                 : "=r"(r0), "=r"(r1), "=r"(r2), "=r"(r3) : "r"(addr));
}

// int8 IMMA: m16n8k32, s32 accumulate.
__device__ __forceinline__ void mma16832(int* d, u32 a0, u32 a1, u32 a2, u32 a3,
                                         u32 b0, u32 b1) {
    asm volatile("mma.sync.aligned.m16n8k32.row.col.s32.s8.s8.s32 "
                 "{%0,%1,%2,%3}, {%4,%5,%6,%7}, {%8,%9}, {%0,%1,%2,%3};"
                 : "+r"(d[0]), "+r"(d[1]), "+r"(d[2]), "+r"(d[3])
                 : "r"(a0), "r"(a1), "r"(a2), "r"(a3), "r"(b0), "r"(b1));
}

// packed fp32x2 FMA (even/odd K partial sums; zero precision loss)
__device__ __forceinline__ void fma2(ull &d, ull a, ull b) {
    asm("fma.rn.f32x2 %0, %1, %2, %3;" : "=l"(d) : "l"(a), "l"(b), "l"(d));
}
__device__ __forceinline__ float2 u2f2(ull v) {
    float2 r;
    r.x = __uint_as_float((unsigned)(v & 0xffffffffull));
    r.y = __uint_as_float((unsigned)(v >> 32));
    return r;
}

// =====================================================================
// Quantization: per-row symmetric int8, one block (256 thr) per row.
// Single kernel covers q rows [0,NTOK) then K rows [NTOK, NTOK+3*SLOTS).
// =====================================================================
__device__ __forceinline__ void quant_row(const float* src, int8_t* dst, float* scale_out) {
    __shared__ float wmax[8];
    const int tid = threadIdx.x;
    float4 v = ((const float4*)src)[tid];
    float m = fmaxf(fmaxf(fabsf(v.x), fabsf(v.y)), fmaxf(fabsf(v.z), fabsf(v.w)));
#pragma unroll
    for (int off = 16; off; off >>= 1)
        m = fmaxf(m, __shfl_xor_sync(0xffffffffu, m, off));
    if ((tid & 31) == 0) wmax[tid >> 5] = m;
    __syncthreads();
    float mm = wmax[0];
#pragma unroll
    for (int w = 1; w < 8; ++w) mm = fmaxf(mm, wmax[w]);
    float inv = (mm > 0.f) ? 127.0f / mm : 0.f;
    int a = __float2int_rn(v.x * inv), b = __float2int_rn(v.y * inv);
    int c = __float2int_rn(v.z * inv), d = __float2int_rn(v.w * inv);
    u32 p = (u32)(a & 255) | ((u32)(b & 255) << 8) | ((u32)(c & 255) << 16) | ((u32)(d & 255) << 24);
    ((u32*)dst)[tid] = p;
    if (tid == 0) *scale_out = (mm > 0.f) ? mm / 127.0f : 0.f;
}

__global__ __launch_bounds__(256)
void conv_kernel(const float* __restrict__ q, const float* __restrict__ Ks) {
    int row = blockIdx.x;
    if (row < NTOK) {
        quant_row(q + (size_t)row * D_MODEL, g_qi8 + (size_t)row * D_MODEL, &g_sq[row]);
    } else {
        int r = row - NTOK;   // lvl*SLOTS + slot
        quant_row(Ks + (size_t)r * D_MODEL, g_ki8 + (size_t)r * D_MODEL, &g_sk[r]);
    }
}

// =====================================================================
// FUSED kernel: blocks [0,768)   = int8 IMMA scores + top-16 filter
//               blocks [768,1792)= router hidden (fp32 FFMA2)
// Scores: EXACT round-8 structure: CTA = 64-token tile, 2-buffer cp.async
// (wait_group 1), 8 warps, warp tile 64x16, top-16 scan by 64 threads.
// =====================================================================
#define N_SCORE_BLK (LEVELS * NTOK / 64)          // 768
#define N_ROUTER_BLK ((NTOK / 64) * (HDIM / 128)) // 1024

// scores smem layout (dynamic) — round-8 sizes
#define SM_A   0                        // [2][64 rows][64 B]   = 8 KB
#define SM_B   8192                     // [2][128 rows][64 B]  = 16 KB
#define SM_S   24576                    // float [64][129]      = 33024 B
#define SM_SAL (SM_S + 64 * 129 * 4)    // float [128]
#define SM_SK  (SM_SAL + 512)           // float [128]
#define SM_SQ  (SM_SK + 512)            // float [64]
#define FUSED_SMEM (SM_SQ + 512)

__device__ __forceinline__ void scores_block(char* dsm, int bid, const float* sal) {
    u32 smb;
    asm("{ .reg .u64 t; cvta.to.shared.u64 t, %1; cvt.u32.u64 %0, t; }" : "=r"(smb) : "l"(dsm));

    const int tid  = threadIdx.x;
    const int lane = tid & 31;
    const int wn   = tid >> 5;             // 0..7, 16 slots each
    const int lvl   = bid >> 8;            // 256 token-tiles per level
    const int ttile = bid & 255;

    const char* qg = (const char*)g_qi8 + (size_t)ttile * 64 * 1024;
    const char* kg = (const char*)g_ki8 + (size_t)lvl * SLOTS * 1024;

    float* sS   = (float*)(dsm + SM_S);
    float* sSal = (float*)(dsm + SM_SAL);
    float* sSk  = (float*)(dsm + SM_SK);
    float* sSq  = (float*)(dsm + SM_SQ);

    if (tid < 64) sSq[tid] = g_sq[ttile * 64 + tid];

    // loader: A 256 x 16B chunks (1/thread), B 512 x 16B chunks (2/thread)
    auto issue = [&](int st, int kc, int buf) {
        const int kb = kc * 64;
        {
            int row = tid >> 2, c = tid & 3;
            u32 sw = (u32)(((c ^ (row & 3)) << 4) + row * 64);
            cp16(smb + SM_A + buf * 4096 + sw, qg + (size_t)row * 1024 + kb + c * 16);
        }
#pragma unroll
        for (int h = 0; h < 2; ++h) {
            int e = tid + 256 * h;
            int row = e >> 2, c = e & 3;
            u32 sw = (u32)(((c ^ (row & 3)) << 4) + row * 64);
            cp16(smb + SM_B + buf * 8192 + sw,
                 kg + (size_t)(st * 128 + row) * 1024 + kb + c * 16);
        }
    };

    int acc[4][2][4];
    float tv[CAND]; int ti[CAND];
#pragma unroll
    for (int k = 0; k < CAND; ++k) { tv[k] = -INFINITY; ti[k] = 0; }

    issue(0, 0, 0); CP_COMMIT();

    for (int st = 0; st < 32; ++st) {
#pragma unroll
        for (int i = 0; i < 4; ++i)
#pragma unroll
            for (int j = 0; j < 2; ++j)
#pragma unroll
                for (int r = 0; r < 4; ++r) acc[i][j][r] = 0;

        for (int kc = 0; kc < 16; ++kc) {
            const int buf = kc & 1;
            bool more = true;
            if (kc + 1 < 16)      { issue(st, kc + 1, buf ^ 1); CP_COMMIT(); }
            else if (st + 1 < 32) { issue(st + 1, 0,  buf ^ 1); CP_COMMIT(); }
            else more = false;
            if (more) CP_WAIT1(); else CP_WAIT0();
            __syncthreads();

            const u32 aB = smb + SM_A + buf * 4096;
            const u32 bB = smb + SM_B + buf * 8192;
            const int mid = lane >> 3, lr = lane & 7;
#pragma unroll
            for (int s = 0; s < 2; ++s) {
                const int c0 = s * 2;        // 32 int8 of k per step
                u32 a[4][4];
#pragma unroll
                for (int i = 0; i < 4; ++i) {
                    int row = i * 16 + (mid & 1) * 8 + lr;
                    int ch  = c0 + (mid >> 1);
                    ldm4(a[i][0], a[i][1], a[i][2], a[i][3],
                         aB + row * 64 + ((ch ^ (row & 3)) << 4));
                }
                u32 b[4];
                {
                    int slot = wn * 16 + (mid >> 1) * 8 + lr;
                    int ch   = c0 + (mid & 1);
                    ldm4(b[0], b[1], b[2], b[3],
                         bB + slot * 64 + ((ch ^ (slot & 3)) << 4));
                }
#pragma unroll
                for (int i = 0; i < 4; ++i)
#pragma unroll
                    for (int j = 0; j < 2; ++j)
                        mma16832(acc[i][j], a[i][0], a[i][1], a[i][2], a[i][3],
                                 b[j * 2], b[j * 2 + 1]);
            }
            __syncthreads();
        }

        // ---- epilogue: stage scaled scores, scan top-16 ----
        if (tid < 128) {
            sSal[tid] = sal[lvl * SLOTS + st * 128 + tid];
            sSk[tid]  = g_sk[lvl * SLOTS + st * 128 + tid];
        }
#pragma unroll
        for (int i = 0; i < 4; ++i) {
            int r0 = i * 16 + (lane >> 2);
            float s0 = sSq[r0] * 0.03125f;
            float s1 = sSq[r0 + 8] * 0.03125f;
#pragma unroll
            for (int j = 0; j < 2; ++j) {
                int col = wn * 16 + j * 8 + (lane & 3) * 2;
                sS[r0 * 129 + col]           = (float)acc[i][j][0] * s0;
                sS[r0 * 129 + col + 1]       = (float)acc[i][j][1] * s0;
                sS[(r0 + 8) * 129 + col]     = (float)acc[i][j][2] * s1;
                sS[(r0 + 8) * 129 + col + 1] = (float)acc[i][j][3] * s1;
            }
        }
        __syncthreads();

        if (tid < 64) {
#pragma unroll 4
            for (int s = 0; s < 128; ++s) {
                float v = fmaf(sS[tid * 129 + s], sSk[s], sSal[s]);
                if (v > tv[CAND - 1]) {
                    tv[CAND - 1] = v; ti[CAND - 1] = st * 128 + s;
#pragma unroll
                    for (int k = CAND - 1; k > 0; --k) {
                        if (tv[k] > tv[k - 1]) {
                            float a = tv[k]; tv[k] = tv[k - 1]; tv[k - 1] = a;
                            int   b = ti[k]; ti[k] = ti[k - 1]; ti[k - 1] = b;
                        }
                    }
                }
            }
        }
        __syncthreads();
    }

    if (tid < 64) {
        int tok = ttile * 64 + tid;
        size_t cb = ((size_t)lvl * NTOK + tok) * CAND;
#pragma unroll
        for (int k = 0; k < CAND; ++k) g_ci[cb + k] = ti[k];
    }
}

// router hidden h = relu(q @ W1 + b1). fp32 via FFMA2 (precision-critical).
__device__ __forceinline__ void router_block(char* dsm, int bid2,
                                             const float* __restrict__ q,
                                             const float* __restrict__ W1,
                                             const float* __restrict__ b1) {
    ull* qs = (ull*)dsm;             // 64*8 entries = 4 KB
    ull* bs = (ull*)(dsm + 4096);    // 8*128 entries = 8 KB

    const int tid = threadIdx.x;
    const int tx = tid & 15;
    const int ty = tid >> 4;
    const int tok0 = (bid2 & 255) * 64;
    const int n0   = (bid2 >> 8) * 128;

    const float* qbase = q + (size_t)tok0 * D_MODEL;
    const int l_r  = tid >> 3;
    const int l_kp = tid & 7;

    ull acc[4][8];
#pragma unroll
    for (int j = 0; j < 4; ++j)
#pragma unroll
        for (int i = 0; i < 8; ++i) acc[j][i] = 0ull;

    float2 pq[2];
    float  pb[8];
#pragma unroll
    for (int j = 0; j < 2; ++j)
        pq[j] = *(const float2*)(qbase + (size_t)(l_r + 32 * j) * D_MODEL + 2 * l_kp);
#pragma unroll
    for (int i = 0; i < 8; ++i) {
        int e = tid + 256 * i;
        int k = e >> 7, nl = e & 127;
        pb[i] = W1[(size_t)k * HDIM + n0 + nl];
    }

    for (int kc = 0; kc < D_MODEL / 16; ++kc) {
        __syncthreads();
#pragma unroll
        for (int j = 0; j < 2; ++j)
            ((float2*)qs)[(l_r + 32 * j) * 8 + l_kp] = pq[j];
#pragma unroll
        for (int i = 0; i < 8; ++i) {
            int e = tid + 256 * i;
            int k = e >> 7, nl = e & 127;
            int kp = k >> 1, par = k & 1;
            ((float*)bs)[(kp * 128 + (nl ^ (kp << 2))) * 2 + par] = pb[i];
        }
        __syncthreads();

        if (kc + 1 < D_MODEL / 16) {
            const int kb = (kc + 1) * 16;
#pragma unroll
            for (int j = 0; j < 2; ++j)
                pq[j] = *(const float2*)(qbase + (size_t)(l_r + 32 * j) * D_MODEL + kb + 2 * l_kp);
#pragma unroll
            for (int i = 0; i < 8; ++i) {
                int e = tid + 256 * i;
                int k = e >> 7, nl = e & 127;
                pb[i] = W1[(size_t)(kb + k) * HDIM + n0 + nl];
            }
        }

#pragma unroll
        for (int kp = 0; kp < 8; ++kp) {
            ull qq0 = qs[(ty +  0) * 8 + kp];
            ull qq1 = qs[(ty + 16) * 8 + kp];
            ull qq2 = qs[(ty + 32) * 8 + kp];
            ull qq3 = qs[(ty + 48) * 8 + kp];
#pragma unroll
            for (int i = 0; i < 8; ++i) {
                ull kk = bs[kp * 128 + ((tx + 16 * i) ^ (kp << 2))];
                fma2(acc[0][i], qq0, kk);
                fma2(acc[1][i], qq1, kk);
                fma2(acc[2][i], qq2, kk);
                fma2(acc[3][i], qq3, kk);
            }
        }
    }

#pragma unroll
    for (int j = 0; j < 4; ++j)
#pragma unroll
        for (int i = 0; i < 8; ++i) {
            int t = ty + 16 * j;
            int n = tx + 16 * i;
            float2 a = u2f2(acc[j][i]);
            float v = a.x + a.y + b1[n0 + n];
            g_h[(size_t)(tok0 + t) * HDIM + n0 + n] = fmaxf(v, 0.0f);
        }
}

__global__ __launch_bounds__(256, 2)
void fused_scores_router_kernel(const float* __restrict__ sal,
                                const float* __restrict__ q,
                                const float* __restrict__ W1,
                                const float* __restrict__ b1) {
    extern __shared__ char dsm[];
    const int bid = blockIdx.x;
    if (bid < N_SCORE_BLK) scores_block(dsm, bid, sal);
    else                   router_block(dsm, bid - N_SCORE_BLK, q, W1, b1);
}

// =====================================================================
// Route weights = softmax(h @ W2 + b2). One warp per token.
// =====================================================================
__global__ void route_kernel(const float* __restrict__ W2,
                             const float* __restrict__ b2)
{
    int gw = (blockIdx.x * blockDim.x + threadIdx.x) >> 5;
    int lane = threadIdx.x & 31;
    if (gw >= NTOK) return;

    const float* hr = g_h + (size_t)gw * HDIM;
    float a0 = 0.f, a1 = 0.f, a2 = 0.f;
    for (int i = lane; i < HDIM; i += 32) {
        float hv = hr[i];
        a0 = fmaf(hv, W2[i * 3 + 0], a0);
        a1 = fmaf(hv, W2[i * 3 + 1], a1);
        a2 = fmaf(hv, W2[i * 3 + 2], a2);
    }
#pragma unroll
    for (int off = 16; off; off >>= 1) {
        a0 += __shfl_down_sync(0xffffffffu, a0, off);
        a1 += __shfl_down_sync(0xffffffffu, a1, off);
        a2 += __shfl_down_sync(0xffffffffu, a2, off);
    }
    if (lane == 0) {
        a0 += b2[0]; a1 += b2[1]; a2 += b2[2];
        float m = fmaxf(a0, fmaxf(a1, a2));
        float e0 = expf(a0 - m), e1 = expf(a1 - m), e2 = expf(a2 - m);
        float inv = 1.0f / (e0 + e1 + e2);
        g_route[gw * 3 + 0] = e0 * inv;
        g_route[gw * 3 + 1] = e1 * inv;
        g_route[gw * 3 + 2] = e2 * inv;
    }
}

// =====================================================================
// Rescore candidates exactly in fp32, top-8-of-16 (jax tie-break: lower
// slot first), softmax, route-weighted V gather, sum levels -> output.
// One block per token, 256 threads. Each warp runs 2 candidates per round
// (3 rounds) with 4 independent partial accumulators each (MLP/ILP).
// =====================================================================
__global__ __launch_bounds__(256)
void rescore_out_kernel(const float* __restrict__ q,
                        const float* __restrict__ Ks,
                        const float* __restrict__ Vs,
                        const float* __restrict__ sal,
                        float* __restrict__ out)
{
    __shared__ float qs[D_MODEL];
    __shared__ float csc[LEVELS][CAND];
    __shared__ int   csl[LEVELS][CAND];
    __shared__ float w8[LEVELS][TOPK];
    __shared__ int   i8[LEVELS][TOPK];

    const int tok = blockIdx.x;
    const int tid = threadIdx.x;
    ((float4*)qs)[tid] = ((const float4*)(q + (size_t)tok * D_MODEL))[tid];
    if (tid < LEVELS * CAND) {
        int l = tid / CAND, c = tid % CAND;
        csl[l][c] = g_ci[((size_t)l * NTOK + tok) * CAND + c];
    }
    __syncthreads();

    const int w = tid >> 5, lane = tid & 31;
#pragma unroll
    for (int r = 0; r < 3; ++r) {
        int d0 = w + r * 16;
        int d1 = d0 + 8;
        int l0 = d0 / CAND, c0 = d0 - l0 * CAND;
        int l1 = d1 / CAND, c1 = d1 - l1 * CAND;
        int s0 = csl[l0][c0], s1 = csl[l1][c1];
        const float* k0 = Ks + ((size_t)l0 * SLOTS + s0) * D_MODEL;
        const float* k1 = Ks + ((size_t)l1 * SLOTS + s1) * D_MODEL;
        float A[4] = {0.f, 0.f, 0.f, 0.f};
        float B[4] = {0.f, 0.f, 0.f, 0.f};
#pragma unroll
        for (int i = 0; i < 8; ++i) {
            int o = lane * 4 + i * 128;
            float4 qv  = *(const float4*)(qs + o);
            float4 k0v = *(const float4*)(k0 + o);
            float4 k1v = *(const float4*)(k1 + o);
            A[0] = fmaf(qv.x, k0v.x, A[0]); A[1] = fmaf(qv.y, k0v.y, A[1]);
            A[2] = fmaf(qv.z, k0v.z, A[2]); A[3] = fmaf(qv.w, k0v.w, A[3]);
            B[0] = fmaf(qv.x, k1v.x, B[0]); B[1] = fmaf(qv.y, k1v.y, B[1]);
            B[2] = fmaf(qv.z, k1v.z, B[2]); B[3] = fmaf(qv.w, k1v.w, B[3]);
        }
        float sa = (A[0] + A[1]) + (A[2] + A[3]);
        float sb = (B[0] + B[1]) + (B[2] + B[3]);
#pragma unroll
        for (int off = 16; off; off >>= 1) {
            sa += __shfl_down_sync(0xffffffffu, sa, off);
            sb += __shfl_down_sync(0xffffffffu, sb, off);
        }
        if (lane == 0) {
            csc[l0][c0] = fmaf(sa, 0.03125f, __ldg(&sal[l0 * SLOTS + s0]));
            csc[l1][c1] = fmaf(sb, 0.03125f, __ldg(&sal[l1 * SLOTS + s1]));
        }
    }
    __syncthreads();

    if (tid < LEVELS) {
        int l = tid;
        float lv[CAND]; int li[CAND];
#pragma unroll
        for (int c = 0; c < CAND; ++c) { lv[c] = csc[l][c]; li[c] = csl[l][c]; }
        float sv[TOPK]; int si[TOPK];
#pragma unroll
        for (int k = 0; k < TOPK; ++k) {
            int bj = 0;
#pragma unroll
            for (int c = 1; c < CAND; ++c) {
                bool better = (lv[c] > lv[bj]) || (lv[c] == lv[bj] && li[c] < li[bj]);
                if (better) bj = c;
            }
            sv[k] = lv[bj]; si[k] = li[bj]; lv[bj] = -INFINITY;
        }
        float m = sv[0];
#pragma unroll
        for (int k = 1; k < TOPK; ++k) m = fmaxf(m, sv[k]);
        float sum = 0.f, e[TOPK];
#pragma unroll
        for (int k = 0; k < TOPK; ++k) { e[k] = expf(sv[k] - m); sum += e[k]; }
        float sc = g_route[tok * 3 + l] / sum;
#pragma unroll
        for (int k = 0; k < TOPK; ++k) { w8[l][k] = e[k] * sc; i8[l][k] = si[k]; }
    }
    __syncthreads();

    float4 o = make_float4(0.f, 0.f, 0.f, 0.f);
#pragma unroll
    for (int l = 0; l < LEVELS; ++l) {
#pragma unroll
        for (int k = 0; k < TOPK; ++k) {
            float ww = w8[l][k];
            const float4* vr = (const float4*)(Vs + ((size_t)l * SLOTS + i8[l][k]) * D_MODEL) + tid;
            float4 vv = *vr;
            o.x = fmaf(ww, vv.x, o.x); o.y = fmaf(ww, vv.y, o.y);
            o.z = fmaf(ww, vv.z, o.z); o.w = fmaf(ww, vv.w, o.w);
        }
    }
    ((float4*)(out + (size_t)tok * D_MODEL))[tid] = o;
}

// =====================================================================
extern "C" void kernel_launch(void* const* d_in, const int* in_sizes, int n_in,
                              void* d_out, int out_size)
{
    (void)in_sizes; (void)n_in; (void)out_size;
    const float* q    = (const float*)d_in[0];
    const float* Ksm  = (const float*)d_in[1];
    const float* Vsm  = (const float*)d_in[2];
    const float* sal  = (const float*)d_in[3];
    const float* W1   = (const float*)d_in[4];
    const float* b1   = (const float*)d_in[5];
    const float* W2   = (const float*)d_in[6];
    const float* b2   = (const float*)d_in[7];
    float* out = (float*)d_out;

    cudaFuncSetAttribute(fused_scores_router_kernel,
                         cudaFuncAttributeMaxDynamicSharedMemorySize, FUSED_SMEM);

    conv_kernel<<<NTOK + LEVELS * SLOTS, 256>>>(q, Ksm);
    fused_scores_router_kernel<<<N_SCORE_BLK + N_ROUTER_BLK, 256, FUSED_SMEM>>>(sal, q, W1, b1);
    route_kernel<<<NTOK / 4, 128>>>(W2, b2);
    rescore_out_kernel<<<NTOK, 256>>>(q, Ksm, Vsm, sal, out);
}

// round 12
// speedup vs baseline: 1.3669x; 1.0310x over previous
#include <cuda_runtime.h>
#include <cuda_bf16.h>
#include <math.h>
#include <stdint.h>

#define D_MODEL 1024
#define HDIM    512
#define SLOTS   4096
#define LEVELS  3
#define NTOK    16384
#define TOPK    8
#define CAND    16

typedef unsigned long long ull;
typedef unsigned int u32;

// ---------------- scratch (static __device__, no allocations) ----------------
__device__ int8_t g_qi8[(size_t)NTOK * D_MODEL];                  // 16 MB int8 q
__device__ int8_t g_ki8[(size_t)LEVELS * SLOTS * D_MODEL];        // 12 MB int8 K
__device__ float  g_sq[NTOK];                                     // per-token scale
__device__ float  g_sk[LEVELS * SLOTS];                           // per-slot scale
__device__ float  g_h[(size_t)NTOK * HDIM];                       // router hidden
__device__ float  g_route[NTOK * LEVELS];                         // route weights
__device__ int    g_ci[(size_t)LEVELS * NTOK * CAND];             // top-16 candidates

// ---------------- PTX helpers (baseline-ISA only) ----------------
__device__ __forceinline__ void cp16(u32 dst, const void* src) {
    asm volatile("cp.async.cg.shared.global [%0], [%1], 16;" :: "r"(dst), "l"(src) : "memory");
}
#define CP_COMMIT() asm volatile("cp.async.commit_group;" ::: "memory")
#define CP_WAIT1()  asm volatile("cp.async.wait_group 1;" ::: "memory")
#define CP_WAIT0()  asm volatile("cp.async.wait_group 0;" ::: "memory")

__device__ __forceinline__ void ldm4(u32 &r0, u32 &r1, u32 &r2, u32 &r3, u32 addr) {
    asm volatile("ldmatrix.sync.aligned.m8n8.x4.shared.b16 {%0,%1,%2,%3}, [%4];"
                 : "=r"(r0), "=r"(r1), "=r"(r2), "=r"(r3) : "r"(addr));
}

// int8 IMMA: m16n8k32, s32 accumulate.
__device__ __forceinline__ void mma16832(int* d, u32 a0, u32 a1, u32 a2, u32 a3,
                                         u32 b0, u32 b1) {
    asm volatile("mma.sync.aligned.m16n8k32.row.col.s32.s8.s8.s32 "
                 "{%0,%1,%2,%3}, {%4,%5,%6,%7}, {%8,%9}, {%0,%1,%2,%3};"
                 : "+r"(d[0]), "+r"(d[1]), "+r"(d[2]), "+r"(d[3])
                 : "r"(a0), "r"(a1), "r"(a2), "r"(a3), "r"(b0), "r"(b1));
}

// packed fp32x2 FMA (even/odd K partial sums; zero precision loss)
__device__ __forceinline__ void fma2(ull &d, ull a, ull b) {
    asm("fma.rn.f32x2 %0, %1, %2, %3;" : "=l"(d) : "l"(a), "l"(b), "l"(d));
}
__device__ __forceinline__ float2 u2f2(ull v) {
    float2 r;
    r.x = __uint_as_float((unsigned)(v & 0xffffffffull));
    r.y = __uint_as_float((unsigned)(v >> 32));
    return r;
}

// =====================================================================
// Quantization: per-row symmetric int8, one block (256 thr) per row.
// Single kernel covers q rows [0,NTOK) then K rows [NTOK, NTOK+3*SLOTS).
// =====================================================================
__device__ __forceinline__ void quant_row(const float* src, int8_t* dst, float* scale_out) {
    __shared__ float wmax[8];
    const int tid = threadIdx.x;
    float4 v = __ldcs(((const float4*)src) + tid);   // single-use stream: don't pollute L2
    float m = fmaxf(fmaxf(fabsf(v.x), fabsf(v.y)), fmaxf(fabsf(v.z), fabsf(v.w)));
#pragma unroll
    for (int off = 16; off; off >>= 1)
        m = fmaxf(m, __shfl_xor_sync(0xffffffffu, m, off));
    if ((tid & 31) == 0) wmax[tid >> 5] = m;
    __syncthreads();
    float mm = wmax[0];
#pragma unroll
    for (int w = 1; w < 8; ++w) mm = fmaxf(mm, wmax[w]);
    float inv = (mm > 0.f) ? 127.0f / mm : 0.f;
    int a = __float2int_rn(v.x * inv), b = __float2int_rn(v.y * inv);
    int c = __float2int_rn(v.z * inv), d = __float2int_rn(v.w * inv);
    u32 p = (u32)(a & 255) | ((u32)(b & 255) << 8) | ((u32)(c & 255) << 16) | ((u32)(d & 255) << 24);
    ((u32*)dst)[tid] = p;
    if (tid == 0) *scale_out = (mm > 0.f) ? mm / 127.0f : 0.f;
}

__global__ __launch_bounds__(256)
void conv_kernel(const float* __restrict__ q, const float* __restrict__ Ks) {
    int row = blockIdx.x;
    if (row < NTOK) {
        quant_row(q + (size_t)row * D_MODEL, g_qi8 + (size_t)row * D_MODEL, &g_sq[row]);
    } else {
        int r = row - NTOK;   // lvl*SLOTS + slot
        quant_row(Ks + (size_t)r * D_MODEL, g_ki8 + (size_t)r * D_MODEL, &g_sk[r]);
    }
}

// =====================================================================
// FUSED kernel: blocks [0,768)   = int8 IMMA scores + top-16 filter
//               blocks [768,1792)= router hidden (fp32 FFMA2)
// Scores: EXACT round-8 structure: CTA = 64-token tile, 2-buffer cp.async
// (wait_group 1), 8 warps, warp tile 64x16, top-16 scan by 64 threads.
// =====================================================================
#define N_SCORE_BLK (LEVELS * NTOK / 64)          // 768
#define N_ROUTER_BLK ((NTOK / 64) * (HDIM / 128)) // 1024

// scores smem layout (dynamic) — round-8 sizes
#define SM_A   0                        // [2][64 rows][64 B]   = 8 KB
#define SM_B   8192                     // [2][128 rows][64 B]  = 16 KB
#define SM_S   24576                    // float [64][129]      = 33024 B
#define SM_SAL (SM_S + 64 * 129 * 4)    // float [128]
#define SM_SK  (SM_SAL + 512)           // float [128]
#define SM_SQ  (SM_SK + 512)            // float [64]
#define FUSED_SMEM (SM_SQ + 512)

__device__ __forceinline__ void scores_block(char* dsm, int bid, const float* sal) {
    u32 smb;
    asm("{ .reg .u64 t; cvta.to.shared.u64 t, %1; cvt.u32.u64 %0, t; }" : "=r"(smb) : "l"(dsm));

    const int tid  = threadIdx.x;
    const int lane = tid & 31;
    const int wn   = tid >> 5;             // 0..7, 16 slots each
    const int lvl   = bid >> 8;            // 256 token-tiles per level
    const int ttile = bid & 255;

    const char* qg = (const char*)g_qi8 + (size_t)ttile * 64 * 1024;
    const char* kg = (const char*)g_ki8 + (size_t)lvl * SLOTS * 1024;

    float* sS   = (float*)(dsm + SM_S);
    float* sSal = (float*)(dsm + SM_SAL);
    float* sSk  = (float*)(dsm + SM_SK);
    float* sSq  = (float*)(dsm + SM_SQ);

    if (tid < 64) sSq[tid] = g_sq[ttile * 64 + tid];

    // loader: A 256 x 16B chunks (1/thread), B 512 x 16B chunks (2/thread)
    auto issue = [&](int st, int kc, int buf) {
        const int kb = kc * 64;
        {
            int row = tid >> 2, c = tid & 3;
            u32 sw = (u32)(((c ^ (row & 3)) << 4) + row * 64);
            cp16(smb + SM_A + buf * 4096 + sw, qg + (size_t)row * 1024 + kb + c * 16);
        }
#pragma unroll
        for (int h = 0; h < 2; ++h) {
            int e = tid + 256 * h;
            int row = e >> 2, c = e & 3;
            u32 sw = (u32)(((c ^ (row & 3)) << 4) + row * 64);
            cp16(smb + SM_B + buf * 8192 + sw,
                 kg + (size_t)(st * 128 + row) * 1024 + kb + c * 16);
        }
    };

    int acc[4][2][4];
    float tv[CAND]; int ti[CAND];
#pragma unroll
    for (int k = 0; k < CAND; ++k) { tv[k] = -INFINITY; ti[k] = 0; }

    issue(0, 0, 0); CP_COMMIT();

    for (int st = 0; st < 32; ++st) {
#pragma unroll
        for (int i = 0; i < 4; ++i)
#pragma unroll
            for (int j = 0; j < 2; ++j)
#pragma unroll
                for (int r = 0; r < 4; ++r) acc[i][j][r] = 0;

        for (int kc = 0; kc < 16; ++kc) {
            const int buf = kc & 1;
            bool more = true;
            if (kc + 1 < 16)      { issue(st, kc + 1, buf ^ 1); CP_COMMIT(); }
            else if (st + 1 < 32) { issue(st + 1, 0,  buf ^ 1); CP_COMMIT(); }
            else more = false;
            if (more) CP_WAIT1(); else CP_WAIT0();
            __syncthreads();

            const u32 aB = smb + SM_A + buf * 4096;
            const u32 bB = smb + SM_B + buf * 8192;
            const int mid = lane >> 3, lr = lane & 7;
#pragma unroll
            for (int s = 0; s < 2; ++s) {
                const int c0 = s * 2;        // 32 int8 of k per step
                u32 a[4][4];
#pragma unroll
                for (int i = 0; i < 4; ++i) {
                    int row = i * 16 + (mid & 1) * 8 + lr;
                    int ch  = c0 + (mid >> 1);
                    ldm4(a[i][0], a[i][1], a[i][2], a[i][3],
                         aB + row * 64 + ((ch ^ (row & 3)) << 4));
                }
                u32 b[4];
                {
                    int slot = wn * 16 + (mid >> 1) * 8 + lr;
                    int ch   = c0 + (mid & 1);
                    ldm4(b[0], b[1], b[2], b[3],
                         bB + slot * 64 + ((ch ^ (slot & 3)) << 4));
                }
#pragma unroll
                for (int i = 0; i < 4; ++i)
#pragma unroll
                    for (int j = 0; j < 2; ++j)
                        mma16832(acc[i][j], a[i][0], a[i][1], a[i][2], a[i][3],
                                 b[j * 2], b[j * 2 + 1]);
            }
            __syncthreads();
        }

        // ---- epilogue: stage scaled scores, scan top-16 ----
        if (tid < 128) {
            sSal[tid] = sal[lvl * SLOTS + st * 128 + tid];
            sSk[tid]  = g_sk[lvl * SLOTS + st * 128 + tid];
        }
#pragma unroll
        for (int i = 0; i < 4; ++i) {
            int r0 = i * 16 + (lane >> 2);
            float s0 = sSq[r0] * 0.03125f;
            float s1 = sSq[r0 + 8] * 0.03125f;
#pragma unroll
            for (int j = 0; j < 2; ++j) {
                int col = wn * 16 + j * 8 + (lane & 3) * 2;
                sS[r0 * 129 + col]           = (float)acc[i][j][0] * s0;
                sS[r0 * 129 + col + 1]       = (float)acc[i][j][1] * s0;
                sS[(r0 + 8) * 129 + col]     = (float)acc[i][j][2] * s1;
                sS[(r0 + 8) * 129 + col + 1] = (float)acc[i][j][3] * s1;
            }
        }
        __syncthreads();

        if (tid < 64) {
#pragma unroll 4
            for (int s = 0; s < 128; ++s) {
                float v = fmaf(sS[tid * 129 + s], sSk[s], sSal[s]);
                if (v > tv[CAND - 1]) {
                    tv[CAND - 1] = v; ti[CAND - 1] = st * 128 + s;
#pragma unroll
                    for (int k = CAND - 1; k > 0; --k) {
                        if (tv[k] > tv[k - 1]) {
                            float a = tv[k]; tv[k] = tv[k - 1]; tv[k - 1] = a;
                            int   b = ti[k]; ti[k] = ti[k - 1]; ti[k - 1] = b;
                        }
                    }
                }
            }
        }
        __syncthreads();
    }

    if (tid < 64) {
        int tok = ttile * 64 + tid;
        size_t cb = ((size_t)lvl * NTOK + tok) * CAND;
#pragma unroll
        for (int k = 0; k < CAND; ++k) g_ci[cb + k] = ti[k];
    }
}

// router hidden h = relu(q @ W1 + b1). fp32 via FFMA2 (precision-critical).
__device__ __forceinline__ void router_block(char* dsm, int bid2,
                                             const float* __restrict__ q,
                                             const float* __restrict__ W1,
                                             const float* __restrict__ b1) {
    ull* qs = (ull*)dsm;             // 64*8 entries = 4 KB
    ull* bs = (ull*)(dsm + 4096);    // 8*128 entries = 8 KB

    const int tid = threadIdx.x;
    const int tx = tid & 15;
    const int ty = tid >> 4;
    const int tok0 = (bid2 & 255) * 64;
    const int n0   = (bid2 >> 8) * 128;

    const float* qbase = q + (size_t)tok0 * D_MODEL;
    const int l_r  = tid >> 3;
    const int l_kp = tid & 7;

    ull acc[4][8];
#pragma unroll
    for (int j = 0; j < 4; ++j)
#pragma unroll
        for (int i = 0; i < 8; ++i) acc[j][i] = 0ull;

    float2 pq[2];
    float  pb[8];
#pragma unroll
    for (int j = 0; j < 2; ++j)
        pq[j] = *(const float2*)(qbase + (size_t)(l_r + 32 * j) * D_MODEL + 2 * l_kp);
#pragma unroll
    for (int i = 0; i < 8; ++i) {
        int e = tid + 256 * i;
        int k = e >> 7, nl = e & 127;
        pb[i] = W1[(size_t)k * HDIM + n0 + nl];
    }

    for (int kc = 0; kc < D_MODEL / 16; ++kc) {
        __syncthreads();
#pragma unroll
        for (int j = 0; j < 2; ++j)
            ((float2*)qs)[(l_r + 32 * j) * 8 + l_kp] = pq[j];
#pragma unroll
        for (int i = 0; i < 8; ++i) {
            int e = tid + 256 * i;
            int k = e >> 7, nl = e & 127;
            int kp = k >> 1, par = k & 1;
            ((float*)bs)[(kp * 128 + (nl ^ (kp << 2))) * 2 + par] = pb[i];
        }
        __syncthreads();

        if (kc + 1 < D_MODEL / 16) {
            const int kb = (kc + 1) * 16;
#pragma unroll
            for (int j = 0; j < 2; ++j)
                pq[j] = *(const float2*)(qbase + (size_t)(l_r + 32 * j) * D_MODEL + kb + 2 * l_kp);
#pragma unroll
            for (int i = 0; i < 8; ++i) {
                int e = tid + 256 * i;
                int k = e >> 7, nl = e & 127;
                pb[i] = W1[(size_t)(kb + k) * HDIM + n0 + nl];
            }
        }

#pragma unroll
        for (int kp = 0; kp < 8; ++kp) {
            ull qq0 = qs[(ty +  0) * 8 + kp];
            ull qq1 = qs[(ty + 16) * 8 + kp];
            ull qq2 = qs[(ty + 32) * 8 + kp];
            ull qq3 = qs[(ty + 48) * 8 + kp];
#pragma unroll
            for (int i = 0; i < 8; ++i) {
                ull kk = bs[kp * 128 + ((tx + 16 * i) ^ (kp << 2))];
                fma2(acc[0][i], qq0, kk);
                fma2(acc[1][i], qq1, kk);
                fma2(acc[2][i], qq2, kk);
                fma2(acc[3][i], qq3, kk);
            }
        }
    }

#pragma unroll
    for (int j = 0; j < 4; ++j)
#pragma unroll
        for (int i = 0; i < 8; ++i) {
            int t = ty + 16 * j;
            int n = tx + 16 * i;
            float2 a = u2f2(acc[j][i]);
            float v = a.x + a.y + b1[n0 + n];
            g_h[(size_t)(tok0 + t) * HDIM + n0 + n] = fmaxf(v, 0.0f);
        }
}

__global__ __launch_bounds__(256, 2)
void fused_scores_router_kernel(const float* __restrict__ sal,
                                const float* __restrict__ q,
                                const float* __restrict__ W1,
                                const float* __restrict__ b1) {
    extern __shared__ char dsm[];
    const int bid = blockIdx.x;
    if (bid < N_SCORE_BLK) scores_block(dsm, bid, sal);
    else                   router_block(dsm, bid - N_SCORE_BLK, q, W1, b1);
}

// =====================================================================
// Route weights = softmax(h @ W2 + b2). One warp per token.
// =====================================================================
__global__ void route_kernel(const float* __restrict__ W2,
                             const float* __restrict__ b2)
{
    int gw = (blockIdx.x * blockDim.x + threadIdx.x) >> 5;
    int lane = threadIdx.x & 31;
    if (gw >= NTOK) return;

    const float* hr = g_h + (size_t)gw * HDIM;
    float a0 = 0.f, a1 = 0.f, a2 = 0.f;
    for (int i = lane; i < HDIM; i += 32) {
        float hv = hr[i];
        a0 = fmaf(hv, W2[i * 3 + 0], a0);
        a1 = fmaf(hv, W2[i * 3 + 1], a1);
        a2 = fmaf(hv, W2[i * 3 + 2], a2);
    }
#pragma unroll
    for (int off = 16; off; off >>= 1) {
        a0 += __shfl_down_sync(0xffffffffu, a0, off);
        a1 += __shfl_down_sync(0xffffffffu, a1, off);
        a2 += __shfl_down_sync(0xffffffffu, a2, off);
    }
    if (lane == 0) {
        a0 += b2[0]; a1 += b2[1]; a2 += b2[2];
        float m = fmaxf(a0, fmaxf(a1, a2));
        float e0 = expf(a0 - m), e1 = expf(a1 - m), e2 = expf(a2 - m);
        float inv = 1.0f / (e0 + e1 + e2);
        g_route[gw * 3 + 0] = e0 * inv;
        g_route[gw * 3 + 1] = e1 * inv;
        g_route[gw * 3 + 2] = e2 * inv;
    }
}

// =====================================================================
// Rescore candidates exactly in fp32, top-8-of-16 (jax tie-break: lower
// slot first), softmax, route-weighted V gather, sum levels -> output.
// One block per token, 256 threads. Round-8 structure (48 regs, occ ~60%);
// q load / out store use streaming hints so K/V stay resident in L2.
// =====================================================================
__global__ __launch_bounds__(256)
void rescore_out_kernel(const float* __restrict__ q,
                        const float* __restrict__ Ks,
                        const float* __restrict__ Vs,
                        const float* __restrict__ sal,
                        float* __restrict__ out)
{
    __shared__ float qs[D_MODEL];
    __shared__ float csc[LEVELS][CAND];
    __shared__ int   csl[LEVELS][CAND];
    __shared__ float w8[LEVELS][TOPK];
    __shared__ int   i8[LEVELS][TOPK];

    const int tok = blockIdx.x;
    const int tid = threadIdx.x;
    ((float4*)qs)[tid] = __ldcs(((const float4*)(q + (size_t)tok * D_MODEL)) + tid);
    if (tid < LEVELS * CAND) {
        int l = tid / CAND, c = tid % CAND;
        csl[l][c] = g_ci[((size_t)l * NTOK + tok) * CAND + c];
    }
    __syncthreads();

    const int w = tid >> 5, lane = tid & 31;
    for (int d = w; d < LEVELS * CAND; d += 8) {
        int l = d / CAND, c = d % CAND;
        int slot = csl[l][c];
        const float* kr = Ks + ((size_t)l * SLOTS + slot) * D_MODEL;
        float acc = 0.f;
#pragma unroll
        for (int i = 0; i < 8; ++i) {
            int o = lane * 4 + i * 128;
            float4 kv = *(const float4*)(kr + o);
            float4 qv = *(const float4*)(qs + o);
            acc = fmaf(qv.x, kv.x, acc); acc = fmaf(qv.y, kv.y, acc);
            acc = fmaf(qv.z, kv.z, acc); acc = fmaf(qv.w, kv.w, acc);
        }
#pragma unroll
        for (int off = 16; off; off >>= 1) acc += __shfl_down_sync(0xffffffffu, acc, off);
        if (lane == 0) csc[l][c] = fmaf(acc, 0.03125f, __ldg(&sal[l * SLOTS + slot]));
    }
    __syncthreads();

    if (tid < LEVELS) {
        int l = tid;
        float lv[CAND]; int li[CAND];
#pragma unroll
        for (int c = 0; c < CAND; ++c) { lv[c] = csc[l][c]; li[c] = csl[l][c]; }
        float sv[TOPK]; int si[TOPK];
#pragma unroll
        for (int k = 0; k < TOPK; ++k) {
            int bj = 0;
#pragma unroll
            for (int c = 1; c < CAND; ++c) {
                bool better = (lv[c] > lv[bj]) || (lv[c] == lv[bj] && li[c] < li[bj]);
                if (better) bj = c;
            }
            sv[k] = lv[bj]; si[k] = li[bj]; lv[bj] = -INFINITY;
        }
        float m = sv[0];
#pragma unroll
        for (int k = 1; k < TOPK; ++k) m = fmaxf(m, sv[k]);
        float sum = 0.f, e[TOPK];
#pragma unroll
        for (int k = 0; k < TOPK; ++k) { e[k] = expf(sv[k] - m); sum += e[k]; }
        float sc = g_route[tok * 3 + l] / sum;
#pragma unroll
        for (int k = 0; k < TOPK; ++k) { w8[l][k] = e[k] * sc; i8[l][k] = si[k]; }
    }
    __syncthreads();

    float4 o = make_float4(0.f, 0.f, 0.f, 0.f);
#pragma unroll
    for (int l = 0; l < LEVELS; ++l) {
#pragma unroll
        for (int k = 0; k < TOPK; ++k) {
            float ww = w8[l][k];
            const float4* vr = (const float4*)(Vs + ((size_t)l * SLOTS + i8[l][k]) * D_MODEL) + tid;
            float4 vv = *vr;
            o.x = fmaf(ww, vv.x, o.x); o.y = fmaf(ww, vv.y, o.y);
            o.z = fmaf(ww, vv.z, o.z); o.w = fmaf(ww, vv.w, o.w);
        }
    }
    __stcs(((float4*)(out + (size_t)tok * D_MODEL)) + tid, o);
}

// =====================================================================
extern "C" void kernel_launch(void* const* d_in, const int* in_sizes, int n_in,
                              void* d_out, int out_size)
{
    (void)in_sizes; (void)n_in; (void)out_size;
    const float* q    = (const float*)d_in[0];
    const float* Ksm  = (const float*)d_in[1];
    const float* Vsm  = (const float*)d_in[2];
    const float* sal  = (const float*)d_in[3];
    const float* W1   = (const float*)d_in[4];
    const float* b1   = (const float*)d_in[5];
    const float* W2   = (const float*)d_in[6];
    const float* b2   = (const float*)d_in[7];
    float* out = (float*)d_out;

    cudaFuncSetAttribute(fused_scores_router_kernel,
                         cudaFuncAttributeMaxDynamicSharedMemorySize, FUSED_SMEM);

    conv_kernel<<<NTOK + LEVELS * SLOTS, 256>>>(q, Ksm);
    fused_scores_router_kernel<<<N_SCORE_BLK + N_ROUTER_BLK, 256, FUSED_SMEM>>>(sal, q, W1, b1);
    route_kernel<<<NTOK / 4, 128>>>(W2, b2);
    rescore_out_kernel<<<NTOK, 256>>>(q, Ksm, Vsm, sal, out);
}

// round 13
// speedup vs baseline: 1.3902x; 1.0171x over previous
#include <cuda_runtime.h>
#include <cuda_bf16.h>
#include <math.h>
#include <stdint.h>

#define D_MODEL 1024
#define HDIM    512
#define SLOTS   4096
#define LEVELS  3
#define NTOK    16384
#define TOPK    8
#define CAND    16

typedef unsigned long long ull;
typedef unsigned int u32;

// ---------------- scratch (static __device__, no allocations) ----------------
__device__ int8_t g_qi8[(size_t)NTOK * D_MODEL];                  // 16 MB int8 q
__device__ int8_t g_ki8[(size_t)LEVELS * SLOTS * D_MODEL];        // 12 MB int8 K
__device__ float  g_sq[NTOK];                                     // per-token scale
__device__ float  g_sk[LEVELS * SLOTS];                           // per-slot scale
__device__ float  g_h[(size_t)NTOK * HDIM];                       // router hidden
__device__ float  g_route[NTOK * LEVELS];                         // route weights
__device__ int    g_ci[(size_t)LEVELS * NTOK * CAND];             // top-16 candidates
__device__ float  g_w8[(size_t)NTOK * LEVELS * TOPK];             // attn*route weights
__device__ int    g_i8[(size_t)NTOK * LEVELS * TOPK];             // selected slots

// ---------------- PTX helpers (baseline-ISA only) ----------------
__device__ __forceinline__ void cp16(u32 dst, const void* src) {
    asm volatile("cp.async.cg.shared.global [%0], [%1], 16;" :: "r"(dst), "l"(src) : "memory");
}
#define CP_COMMIT() asm volatile("cp.async.commit_group;" ::: "memory")
#define CP_WAIT1()  asm volatile("cp.async.wait_group 1;" ::: "memory")
#define CP_WAIT0()  asm volatile("cp.async.wait_group 0;" ::: "memory")

__device__ __forceinline__ void ldm4(u32 &r0, u32 &r1, u32 &r2, u32 &r3, u32 addr) {
    asm volatile("ldmatrix.sync.aligned.m8n8.x4.shared.b16 {%0,%1,%2,%3}, [%4];"
                 : "=r"(r0), "=r"(r1), "=r"(r2), "=r"(r3) : "r"(addr));
}

// int8 IMMA: m16n8k32, s32 accumulate.
__device__ __forceinline__ void mma16832(int* d, u32 a0, u32 a1, u32 a2, u32 a3,
                                         u32 b0, u32 b1) {
    asm volatile("mma.sync.aligned.m16n8k32.row.col.s32.s8.s8.s32 "
                 "{%0,%1,%2,%3}, {%4,%5,%6,%7}, {%8,%9}, {%0,%1,%2,%3};"
                 : "+r"(d[0]), "+r"(d[1]), "+r"(d[2]), "+r"(d[3])
                 : "r"(a0), "r"(a1), "r"(a2), "r"(a3), "r"(b0), "r"(b1));
}

// packed fp32x2 FMA (even/odd K partial sums; zero precision loss)
__device__ __forceinline__ void fma2(ull &d, ull a, ull b) {
    asm("fma.rn.f32x2 %0, %1, %2, %3;" : "=l"(d) : "l"(a), "l"(b), "l"(d));
}
__device__ __forceinline__ float2 u2f2(ull v) {
    float2 r;
    r.x = __uint_as_float((unsigned)(v & 0xffffffffull));
    r.y = __uint_as_float((unsigned)(v >> 32));
    return r;
}

// =====================================================================
// Quantization: per-row symmetric int8, one block (256 thr) per row.
// =====================================================================
__device__ __forceinline__ void quant_row(const float* src, int8_t* dst, float* scale_out) {
    __shared__ float wmax[8];
    const int tid = threadIdx.x;
    float4 v = __ldcs(((const float4*)src) + tid);
    float m = fmaxf(fmaxf(fabsf(v.x), fabsf(v.y)), fmaxf(fabsf(v.z), fabsf(v.w)));
#pragma unroll
    for (int off = 16; off; off >>= 1)
        m = fmaxf(m, __shfl_xor_sync(0xffffffffu, m, off));
    if ((tid & 31) == 0) wmax[tid >> 5] = m;
    __syncthreads();
    float mm = wmax[0];
#pragma unroll
    for (int w = 1; w < 8; ++w) mm = fmaxf(mm, wmax[w]);
    float inv = (mm > 0.f) ? 127.0f / mm : 0.f;
    int a = __float2int_rn(v.x * inv), b = __float2int_rn(v.y * inv);
    int c = __float2int_rn(v.z * inv), d = __float2int_rn(v.w * inv);
    u32 p = (u32)(a & 255) | ((u32)(b & 255) << 8) | ((u32)(c & 255) << 16) | ((u32)(d & 255) << 24);
    ((u32*)dst)[tid] = p;
    if (tid == 0) *scale_out = (mm > 0.f) ? mm / 127.0f : 0.f;
}

__global__ __launch_bounds__(256)
void conv_kernel(const float* __restrict__ q, const float* __restrict__ Ks) {
    int row = blockIdx.x;
    if (row < NTOK) {
        quant_row(q + (size_t)row * D_MODEL, g_qi8 + (size_t)row * D_MODEL, &g_sq[row]);
    } else {
        int r = row - NTOK;   // lvl*SLOTS + slot
        quant_row(Ks + (size_t)r * D_MODEL, g_ki8 + (size_t)r * D_MODEL, &g_sk[r]);
    }
}

// =====================================================================
// FUSED kernel: blocks [0,768)   = int8 IMMA scores + top-16 filter
//               blocks [768,1792)= router hidden (fp32 FFMA2)
// (round-8 proven structure, frozen)
// =====================================================================
#define N_SCORE_BLK (LEVELS * NTOK / 64)          // 768
#define N_ROUTER_BLK ((NTOK / 64) * (HDIM / 128)) // 1024

#define SM_A   0                        // [2][64 rows][64 B]   = 8 KB
#define SM_B   8192                     // [2][128 rows][64 B]  = 16 KB
#define SM_S   24576                    // float [64][129]      = 33024 B
#define SM_SAL (SM_S + 64 * 129 * 4)    // float [128]
#define SM_SK  (SM_SAL + 512)           // float [128]
#define SM_SQ  (SM_SK + 512)            // float [64]
#define FUSED_SMEM (SM_SQ + 512)

__device__ __forceinline__ void scores_block(char* dsm, int bid, const float* sal) {
    u32 smb;
    asm("{ .reg .u64 t; cvta.to.shared.u64 t, %1; cvt.u32.u64 %0, t; }" : "=r"(smb) : "l"(dsm));

    const int tid  = threadIdx.x;
    const int lane = tid & 31;
    const int wn   = tid >> 5;             // 0..7, 16 slots each
    const int lvl   = bid >> 8;            // 256 token-tiles per level
    const int ttile = bid & 255;

    const char* qg = (const char*)g_qi8 + (size_t)ttile * 64 * 1024;
    const char* kg = (const char*)g_ki8 + (size_t)lvl * SLOTS * 1024;

    float* sS   = (float*)(dsm + SM_S);
    float* sSal = (float*)(dsm + SM_SAL);
    float* sSk  = (float*)(dsm + SM_SK);
    float* sSq  = (float*)(dsm + SM_SQ);

    if (tid < 64) sSq[tid] = g_sq[ttile * 64 + tid];

    auto issue = [&](int st, int kc, int buf) {
        const int kb = kc * 64;
        {
            int row = tid >> 2, c = tid & 3;
            u32 sw = (u32)(((c ^ (row & 3)) << 4) + row * 64);
            cp16(smb + SM_A + buf * 4096 + sw, qg + (size_t)row * 1024 + kb + c * 16);
        }
#pragma unroll
        for (int h = 0; h < 2; ++h) {
            int e = tid + 256 * h;
            int row = e >> 2, c = e & 3;
            u32 sw = (u32)(((c ^ (row & 3)) << 4) + row * 64);
            cp16(smb + SM_B + buf * 8192 + sw,
                 kg + (size_t)(st * 128 + row) * 1024 + kb + c * 16);
        }
    };

    int acc[4][2][4];
    float tv[CAND]; int ti[CAND];
#pragma unroll
    for (int k = 0; k < CAND; ++k) { tv[k] = -INFINITY; ti[k] = 0; }

    issue(0, 0, 0); CP_COMMIT();

    for (int st = 0; st < 32; ++st) {
#pragma unroll
        for (int i = 0; i < 4; ++i)
#pragma unroll
            for (int j = 0; j < 2; ++j)
#pragma unroll
                for (int r = 0; r < 4; ++r) acc[i][j][r] = 0;

        for (int kc = 0; kc < 16; ++kc) {
            const int buf = kc & 1;
            bool more = true;
            if (kc + 1 < 16)      { issue(st, kc + 1, buf ^ 1); CP_COMMIT(); }
            else if (st + 1 < 32) { issue(st + 1, 0,  buf ^ 1); CP_COMMIT(); }
            else more = false;
            if (more) CP_WAIT1(); else CP_WAIT0();
            __syncthreads();

            const u32 aB = smb + SM_A + buf * 4096;
            const u32 bB = smb + SM_B + buf * 8192;
            const int mid = lane >> 3, lr = lane & 7;
#pragma unroll
            for (int s = 0; s < 2; ++s) {
                const int c0 = s * 2;
                u32 a[4][4];
#pragma unroll
                for (int i = 0; i < 4; ++i) {
                    int row = i * 16 + (mid & 1) * 8 + lr;
                    int ch  = c0 + (mid >> 1);
                    ldm4(a[i][0], a[i][1], a[i][2], a[i][3],
                         aB + row * 64 + ((ch ^ (row & 3)) << 4));
                }
                u32 b[4];
                {
                    int slot = wn * 16 + (mid >> 1) * 8 + lr;
                    int ch   = c0 + (mid & 1);
                    ldm4(b[0], b[1], b[2], b[3],
                         bB + slot * 64 + ((ch ^ (slot & 3)) << 4));
                }
#pragma unroll
                for (int i = 0; i < 4; ++i)
#pragma unroll
                    for (int j = 0; j < 2; ++j)
                        mma16832(acc[i][j], a[i][0], a[i][1], a[i][2], a[i][3],
                                 b[j * 2], b[j * 2 + 1]);
            }
            __syncthreads();
        }

        // ---- epilogue: stage scaled scores, scan top-16 ----
        if (tid < 128) {
            sSal[tid] = sal[lvl * SLOTS + st * 128 + tid];
            sSk[tid]  = g_sk[lvl * SLOTS + st * 128 + tid];
        }
#pragma unroll
        for (int i = 0; i < 4; ++i) {
            int r0 = i * 16 + (lane >> 2);
            float s0 = sSq[r0] * 0.03125f;
            float s1 = sSq[r0 + 8] * 0.03125f;
#pragma unroll
            for (int j = 0; j < 2; ++j) {
                int col = wn * 16 + j * 8 + (lane & 3) * 2;
                sS[r0 * 129 + col]           = (float)acc[i][j][0] * s0;
                sS[r0 * 129 + col + 1]       = (float)acc[i][j][1] * s0;
                sS[(r0 + 8) * 129 + col]     = (float)acc[i][j][2] * s1;
                sS[(r0 + 8) * 129 + col + 1] = (float)acc[i][j][3] * s1;
            }
        }
        __syncthreads();

        if (tid < 64) {
#pragma unroll 4
            for (int s = 0; s < 128; ++s) {
                float v = fmaf(sS[tid * 129 + s], sSk[s], sSal[s]);
                if (v > tv[CAND - 1]) {
                    tv[CAND - 1] = v; ti[CAND - 1] = st * 128 + s;
#pragma unroll
                    for (int k = CAND - 1; k > 0; --k) {
                        if (tv[k] > tv[k - 1]) {
                            float a = tv[k]; tv[k] = tv[k - 1]; tv[k - 1] = a;
                            int   b = ti[k]; ti[k] = ti[k - 1]; ti[k - 1] = b;
                        }
                    }
                }
            }
        }
        __syncthreads();
    }

    if (tid < 64) {
        int tok = ttile * 64 + tid;
        size_t cb = ((size_t)lvl * NTOK + tok) * CAND;
#pragma unroll
        for (int k = 0; k < CAND; ++k) g_ci[cb + k] = ti[k];
    }
}

// router hidden h = relu(q @ W1 + b1). fp32 via FFMA2 (precision-critical).
__device__ __forceinline__ void router_block(char* dsm, int bid2,
                                             const float* __restrict__ q,
                                             const float* __restrict__ W1,
                                             const float* __restrict__ b1) {
    ull* qs = (ull*)dsm;
    ull* bs = (ull*)(dsm + 4096);

    const int tid = threadIdx.x;
    const int tx = tid & 15;
    const int ty = tid >> 4;
    const int tok0 = (bid2 & 255) * 64;
    const int n0   = (bid2 >> 8) * 128;

    const float* qbase = q + (size_t)tok0 * D_MODEL;
    const int l_r  = tid >> 3;
    const int l_kp = tid & 7;

    ull acc[4][8];
#pragma unroll
    for (int j = 0; j < 4; ++j)
#pragma unroll
        for (int i = 0; i < 8; ++i) acc[j][i] = 0ull;

    float2 pq[2];
    float  pb[8];
#pragma unroll
    for (int j = 0; j < 2; ++j)
        pq[j] = *(const float2*)(qbase + (size_t)(l_r + 32 * j) * D_MODEL + 2 * l_kp);
#pragma unroll
    for (int i = 0; i < 8; ++i) {
        int e = tid + 256 * i;
        int k = e >> 7, nl = e & 127;
        pb[i] = W1[(size_t)k * HDIM + n0 + nl];
    }

    for (int kc = 0; kc < D_MODEL / 16; ++kc) {
        __syncthreads();
#pragma unroll
        for (int j = 0; j < 2; ++j)
            ((float2*)qs)[(l_r + 32 * j) * 8 + l_kp] = pq[j];
#pragma unroll
        for (int i = 0; i < 8; ++i) {
            int e = tid + 256 * i;
            int k = e >> 7, nl = e & 127;
            int kp = k >> 1, par = k & 1;
            ((float*)bs)[(kp * 128 + (nl ^ (kp << 2))) * 2 + par] = pb[i];
        }
        __syncthreads();

        if (kc + 1 < D_MODEL / 16) {
            const int kb = (kc + 1) * 16;
#pragma unroll
            for (int j = 0; j < 2; ++j)
                pq[j] = *(const float2*)(qbase + (size_t)(l_r + 32 * j) * D_MODEL + kb + 2 * l_kp);
#pragma unroll
            for (int i = 0; i < 8; ++i) {
                int e = tid + 256 * i;
                int k = e >> 7, nl = e & 127;
                pb[i] = W1[(size_t)(kb + k) * HDIM + n0 + nl];
            }
        }

#pragma unroll
        for (int kp = 0; kp < 8; ++kp) {
            ull qq0 = qs[(ty +  0) * 8 + kp];
            ull qq1 = qs[(ty + 16) * 8 + kp];
            ull qq2 = qs[(ty + 32) * 8 + kp];
            ull qq3 = qs[(ty + 48) * 8 + kp];
#pragma unroll
            for (int i = 0; i < 8; ++i) {
                ull kk = bs[kp * 128 + ((tx + 16 * i) ^ (kp << 2))];
                fma2(acc[0][i], qq0, kk);
                fma2(acc[1][i], qq1, kk);
                fma2(acc[2][i], qq2, kk);
                fma2(acc[3][i], qq3, kk);
            }
        }
    }

#pragma unroll
    for (int j = 0; j < 4; ++j)
#pragma unroll
        for (int i = 0; i < 8; ++i) {
            int t = ty + 16 * j;
            int n = tx + 16 * i;
            float2 a = u2f2(acc[j][i]);
            float v = a.x + a.y + b1[n0 + n];
            g_h[(size_t)(tok0 + t) * HDIM + n0 + n] = fmaxf(v, 0.0f);
        }
}

__global__ __launch_bounds__(256, 2)
void fused_scores_router_kernel(const float* __restrict__ sal,
                                const float* __restrict__ q,
                                const float* __restrict__ W1,
                                const float* __restrict__ b1) {
    extern __shared__ char dsm[];
    const int bid = blockIdx.x;
    if (bid < N_SCORE_BLK) scores_block(dsm, bid, sal);
    else                   router_block(dsm, bid - N_SCORE_BLK, q, W1, b1);
}

// =====================================================================
// Route weights = softmax(h @ W2 + b2). One warp per token.
// =====================================================================
__global__ void route_kernel(const float* __restrict__ W2,
                             const float* __restrict__ b2)
{
    int gw = (blockIdx.x * blockDim.x + threadIdx.x) >> 5;
    int lane = threadIdx.x & 31;
    if (gw >= NTOK) return;

    const float* hr = g_h + (size_t)gw * HDIM;
    float a0 = 0.f, a1 = 0.f, a2 = 0.f;
    for (int i = lane; i < HDIM; i += 32) {
        float hv = hr[i];
        a0 = fmaf(hv, W2[i * 3 + 0], a0);
        a1 = fmaf(hv, W2[i * 3 + 1], a1);
        a2 = fmaf(hv, W2[i * 3 + 2], a2);
    }
#pragma unroll
    for (int off = 16; off; off >>= 1) {
        a0 += __shfl_down_sync(0xffffffffu, a0, off);
        a1 += __shfl_down_sync(0xffffffffu, a1, off);
        a2 += __shfl_down_sync(0xffffffffu, a2, off);
    }
    if (lane == 0) {
        a0 += b2[0]; a1 += b2[1]; a2 += b2[2];
        float m = fmaxf(a0, fmaxf(a1, a2));
        float e0 = expf(a0 - m), e1 = expf(a1 - m), e2 = expf(a2 - m);
        float inv = 1.0f / (e0 + e1 + e2);
        g_route[gw * 3 + 0] = e0 * inv;
        g_route[gw * 3 + 1] = e1 * inv;
        g_route[gw * 3 + 2] = e2 * inv;
    }
}

// =====================================================================
// Phase 1: rescore candidates exactly in fp32 vs K ONLY (K-resident in L2),
// top-8-of-16 select (jax tie-break), softmax, route weight -> g_w8/g_i8.
// Identical arithmetic/order to the round-12 fused version.
// =====================================================================
__global__ __launch_bounds__(256)
void rescore_k_kernel(const float* __restrict__ q,
                      const float* __restrict__ Ks,
                      const float* __restrict__ sal)
{
    __shared__ float qs[D_MODEL];
    __shared__ float csc[LEVELS][CAND];
    __shared__ int   csl[LEVELS][CAND];

    const int tok = blockIdx.x;
    const int tid = threadIdx.x;
    ((float4*)qs)[tid] = __ldcs(((const float4*)(q + (size_t)tok * D_MODEL)) + tid);
    if (tid < LEVELS * CAND) {
        int l = tid / CAND, c = tid % CAND;
        csl[l][c] = g_ci[((size_t)l * NTOK + tok) * CAND + c];
    }
    __syncthreads();

    const int w = tid >> 5, lane = tid & 31;
    for (int d = w; d < LEVELS * CAND; d += 8) {
        int l = d / CAND, c = d % CAND;
        int slot = csl[l][c];
        const float* kr = Ks + ((size_t)l * SLOTS + slot) * D_MODEL;
        float acc = 0.f;
#pragma unroll
        for (int i = 0; i < 8; ++i) {
            int o = lane * 4 + i * 128;
            float4 kv = *(const float4*)(kr + o);
            float4 qv = *(const float4*)(qs + o);
            acc = fmaf(qv.x, kv.x, acc); acc = fmaf(qv.y, kv.y, acc);
            acc = fmaf(qv.z, kv.z, acc); acc = fmaf(qv.w, kv.w, acc);
        }
#pragma unroll
        for (int off = 16; off; off >>= 1) acc += __shfl_down_sync(0xffffffffu, acc, off);
        if (lane == 0) csc[l][c] = fmaf(acc, 0.03125f, __ldg(&sal[l * SLOTS + slot]));
    }
    __syncthreads();

    if (tid < LEVELS) {
        int l = tid;
        float lv[CAND]; int li[CAND];
#pragma unroll
        for (int c = 0; c < CAND; ++c) { lv[c] = csc[l][c]; li[c] = csl[l][c]; }
        float sv[TOPK]; int si[TOPK];
#pragma unroll
        for (int k = 0; k < TOPK; ++k) {
            int bj = 0;
#pragma unroll
            for (int c = 1; c < CAND; ++c) {
                bool better = (lv[c] > lv[bj]) || (lv[c] == lv[bj] && li[c] < li[bj]);
                if (better) bj = c;
            }
            sv[k] = lv[bj]; si[k] = li[bj]; lv[bj] = -INFINITY;
        }
        float m = sv[0];
#pragma unroll
        for (int k = 1; k < TOPK; ++k) m = fmaxf(m, sv[k]);
        float sum = 0.f, e[TOPK];
#pragma unroll
        for (int k = 0; k < TOPK; ++k) { e[k] = expf(sv[k] - m); sum += e[k]; }
        float sc = g_route[tok * 3 + l] / sum;
        size_t ob = ((size_t)tok * LEVELS + l) * TOPK;
#pragma unroll
        for (int k = 0; k < TOPK; ++k) { g_w8[ob + k] = e[k] * sc; g_i8[ob + k] = si[k]; }
    }
}

// =====================================================================
// Phase 2: gather V (V-resident in L2), weighted sum, write output.
// Same per-level/k accumulation order as round 12 -> bit-identical output.
// =====================================================================
__global__ __launch_bounds__(256)
void out_kernel(const float* __restrict__ Vs, float* __restrict__ out)
{
    __shared__ float w8[LEVELS][TOPK];
    __shared__ int   i8[LEVELS][TOPK];

    const int tok = blockIdx.x;
    const int tid = threadIdx.x;
    if (tid < LEVELS * TOPK) {
        int l = tid / TOPK, k = tid % TOPK;
        size_t ob = ((size_t)tok * LEVELS + l) * TOPK + k;
        w8[l][k] = g_w8[ob];
        i8[l][k] = g_i8[ob];
    }
    __syncthreads();

    float4 o = make_float4(0.f, 0.f, 0.f, 0.f);
#pragma unroll
    for (int l = 0; l < LEVELS; ++l) {
#pragma unroll
        for (int k = 0; k < TOPK; ++k) {
            float ww = w8[l][k];
            const float4* vr = (const float4*)(Vs + ((size_t)l * SLOTS + i8[l][k]) * D_MODEL) + tid;
            float4 vv = *vr;
            o.x = fmaf(ww, vv.x, o.x); o.y = fmaf(ww, vv.y, o.y);
            o.z = fmaf(ww, vv.z, o.z); o.w = fmaf(ww, vv.w, o.w);
        }
    }
    __stcs(((float4*)(out + (size_t)tok * D_MODEL)) + tid, o);
}

// =====================================================================
extern "C" void kernel_launch(void* const* d_in, const int* in_sizes, int n_in,
                              void* d_out, int out_size)
{
    (void)in_sizes; (void)n_in; (void)out_size;
    const float* q    = (const float*)d_in[0];
    const float* Ksm  = (const float*)d_in[1];
    const float* Vsm  = (const float*)d_in[2];
    const float* sal  = (const float*)d_in[3];
    const float* W1   = (const float*)d_in[4];
    const float* b1   = (const float*)d_in[5];
    const float* W2   = (const float*)d_in[6];
    const float* b2   = (const float*)d_in[7];
    float* out = (float*)d_out;

    cudaFuncSetAttribute(fused_scores_router_kernel,
                         cudaFuncAttributeMaxDynamicSharedMemorySize, FUSED_SMEM);

    conv_kernel<<<NTOK + LEVELS * SLOTS, 256>>>(q, Ksm);
    fused_scores_router_kernel<<<N_SCORE_BLK + N_ROUTER_BLK, 256, FUSED_SMEM>>>(sal, q, W1, b1);
    route_kernel<<<NTOK / 4, 128>>>(W2, b2);
    rescore_k_kernel<<<NTOK, 256>>>(q, Ksm, sal);
    out_kernel<<<NTOK, 256>>>(Vsm, out);
}